// round 1
// baseline (speedup 1.0000x reference)
#include <cuda_runtime.h>
#include <math.h>

// ---------------------------------------------------------------------------
// Problem constants
// ---------------------------------------------------------------------------
namespace {
constexpr int N_ = 8192;
constexpr int C_ = 64;
constexpr int E_ = 262144;
constexpr int M_ = 2048;

// accumulator slots
enum { A_CE = 0, A_ACCU, A_LS1, A_LS2, A_CON, A_SUP, A_WDS, A_MSK };

// scratch layout (floats)
constexpr size_t OFF_XW   = 0;                               // 8192 x 512
constexpr size_t OFF_H    = OFF_XW   + (size_t)N_ * 512;     // 8192 x 512
constexpr size_t OFF_HW   = OFF_H    + (size_t)N_ * 512;     // 8192 x 128
constexpr size_t OFF_Y    = OFF_HW   + (size_t)N_ * 128;     // 8192 x 128
constexpr size_t OFF_GN   = OFF_Y    + (size_t)N_ * 128;     // 8192 x 64
constexpr size_t OFF_HN   = OFF_GN   + (size_t)N_ * 64;      // 8192 x 64
constexpr size_t OFF_WCAT = OFF_HN   + (size_t)N_ * 64;      // 256 x 512
constexpr size_t OFF_BCAT = OFF_WCAT + 256 * 512;            // 512
constexpr size_t OFF_BCAT2= OFF_BCAT + 512;                  // 128
constexpr size_t OFF_U1   = OFF_BCAT2 + 128;                 // N
constexpr size_t OFF_V1   = OFF_U1 + N_;
constexpr size_t OFF_U2   = OFF_V1 + N_;
constexpr size_t OFF_V2   = OFF_U2 + N_;
constexpr size_t OFF_DG   = OFF_V2 + N_;                     // diag logits
constexpr size_t OFF_RE   = OFF_DG + N_;                     // row sums exp
constexpr size_t OFF_CEc  = OFF_RE + N_;                     // col sums exp
constexpr size_t OFF_G1   = OFF_CEc + N_;                    // 2048 x 64
constexpr size_t OFF_G2   = OFF_G1 + (size_t)M_ * 64;        // 2048 x 64
constexpr size_t OFF_SP1  = OFF_G2 + (size_t)M_ * 64;        // M
constexpr size_t OFF_SN1  = OFF_SP1 + M_;
constexpr size_t OFF_SP2  = OFF_SN1 + M_;
constexpr size_t OFF_SN2  = OFF_SP2 + M_;
constexpr size_t OFF_RSA  = OFF_SN2 + M_;
constexpr size_t OFF_ACC  = OFF_RSA + M_;                    // 64 scalars
constexpr size_t SCR_TOT  = OFF_ACC + 64;
}  // namespace

__device__ __align__(256) float d_scratch[SCR_TOT];

// ---------------------------------------------------------------------------
// helpers
// ---------------------------------------------------------------------------
__device__ __forceinline__ float warp_sum(float v) {
#pragma unroll
    for (int o = 16; o; o >>= 1) v += __shfl_xor_sync(0xffffffffu, v, o);
    return v;
}
__device__ __forceinline__ float warp_max(float v) {
#pragma unroll
    for (int o = 16; o; o >>= 1) v = fmaxf(v, __shfl_xor_sync(0xffffffffu, v, o));
    return v;
}

// block (256 thr) reduce-and-atomic-add
__device__ __forceinline__ void block_atomic_add(float v, float* dst, float* shbuf) {
    int lane = threadIdx.x & 31, wid = threadIdx.x >> 5;
    v = warp_sum(v);
    if (lane == 0) shbuf[wid] = v;
    __syncthreads();
    if (wid == 0) {
        float x = (lane < (int)(blockDim.x >> 5)) ? shbuf[lane] : 0.f;
        x = warp_sum(x);
        if (lane == 0) atomicAdd(dst, x);
    }
    __syncthreads();
}

// ---------------------------------------------------------------------------
// utility kernels
// ---------------------------------------------------------------------------
__global__ void k_zero(float* p, int n) {
    int i = blockIdx.x * blockDim.x + threadIdx.x;
    if (i < n) p[i] = 0.f;
}

__global__ void k_prep(const float* __restrict__ W0, const float* __restrict__ Wh0,
                       const float* __restrict__ b0, const float* __restrict__ bh0,
                       const float* __restrict__ b1, const float* __restrict__ bh1) {
    int i = blockIdx.x * blockDim.x + threadIdx.x;
    if (i < 256 * 256) {
        int d = i >> 8, h = i & 255;
        d_scratch[OFF_WCAT + (size_t)d * 512 + h]       = W0[i];
        d_scratch[OFF_WCAT + (size_t)d * 512 + 256 + h] = Wh0[i];
    }
    if (i < 256) {
        d_scratch[OFF_BCAT + i]       = b0[i];
        d_scratch[OFF_BCAT + 256 + i] = bh0[i];
    }
    if (i < 64) {
        d_scratch[OFF_BCAT2 + i]      = b1[i];
        d_scratch[OFF_BCAT2 + 64 + i] = bh1[i];
    }
}

__global__ void k_masksum(const int* __restrict__ mask) {
    __shared__ float sh[8];
    int i = blockIdx.x * blockDim.x + threadIdx.x;
    float v = (i < N_) ? (float)mask[i] : 0.f;
    block_atomic_add(v, &d_scratch[OFF_ACC + A_MSK], sh);
}

// ---------------------------------------------------------------------------
// generic SGEMM: C[M,N] = op(A[M,K] @ B[K,N] + bias), 64x64x16 tiles, 4x4/thr
// all dims must be multiples of the tile sizes (true for every call here)
// ---------------------------------------------------------------------------
__global__ __launch_bounds__(256) void k_sgemm(
    const float* __restrict__ A, int lda,
    const float* __restrict__ B, int ldb,
    const float* __restrict__ bias,
    float* __restrict__ C, int ldc,
    int K, int relu)
{
    __shared__ float As[16][68];   // [k][m], padded
    __shared__ float Bs[16][64];   // [k][n]
    const int tid = threadIdx.x;
    const int bm = blockIdx.y, bn = blockIdx.x;

    const int aRow = tid >> 2;            // 0..63
    const int aCol = (tid & 3) << 2;      // 0,4,8,12
    const int bRow = tid >> 4;            // 0..15
    const int bCol = (tid & 15) << 2;     // 0..60

    const float* Ap = A + (size_t)(bm * 64 + aRow) * lda + aCol;
    const float* Bp = B + (size_t)bRow * ldb + bn * 64 + bCol;

    const int tr = tid >> 4, tc = tid & 15;

    float acc[4][4];
#pragma unroll
    for (int i = 0; i < 4; i++)
#pragma unroll
        for (int j = 0; j < 4; j++) acc[i][j] = 0.f;

    for (int k0 = 0; k0 < K; k0 += 16) {
        float4 av = *(const float4*)(Ap + k0);
        float4 bv = *(const float4*)(Bp + (size_t)k0 * ldb);
        As[aCol + 0][aRow] = av.x;
        As[aCol + 1][aRow] = av.y;
        As[aCol + 2][aRow] = av.z;
        As[aCol + 3][aRow] = av.w;
        *(float4*)&Bs[bRow][bCol] = bv;
        __syncthreads();
#pragma unroll
        for (int k = 0; k < 16; k++) {
            float4 a4 = *(const float4*)&As[k][tr << 2];
            float4 b4 = *(const float4*)&Bs[k][tc << 2];
            float aa[4] = {a4.x, a4.y, a4.z, a4.w};
            float bb[4] = {b4.x, b4.y, b4.z, b4.w};
#pragma unroll
            for (int i = 0; i < 4; i++)
#pragma unroll
                for (int j = 0; j < 4; j++) acc[i][j] = fmaf(aa[i], bb[j], acc[i][j]);
        }
        __syncthreads();
    }

    const int row0 = bm * 64 + (tr << 2);
    const int col0 = bn * 64 + (tc << 2);
#pragma unroll
    for (int i = 0; i < 4; i++) {
#pragma unroll
        for (int j = 0; j < 4; j++) {
            float v = acc[i][j];
            if (bias) v += bias[col0 + j];
            if (relu) v = fmaxf(v, 0.f);
            C[(size_t)(row0 + i) * ldc + col0 + j] = v;
        }
    }
}

// ---------------------------------------------------------------------------
// per-row: l2norms, outputs, CE, accuracy, Wc dots, diag logits
// one block of 32 threads per row; thread t owns cols t and t+32
// ---------------------------------------------------------------------------
__global__ __launch_bounds__(32) void k_rownorm(
    const float* __restrict__ labels, const float* __restrict__ Wc,
    const float* __restrict__ bcp, const int* __restrict__ mask,
    float* __restrict__ outp)
{
    const int r = blockIdx.x;
    const int t = threadIdx.x;
    const float* Y = d_scratch + OFF_Y + (size_t)r * 128;

    float y1a = Y[t],      y1b = Y[t + 32];
    float y2a = Y[64 + t], y2b = Y[96 + t];

    float s1 = warp_sum(y1a * y1a + y1b * y1b);
    float n1 = fmaxf(sqrtf(s1), 1e-12f);
    float ga = y1a / n1, gb = y1b / n1;

    float s2 = warp_sum(y2a * y2a + y2b * y2b);
    float n2 = fmaxf(sqrtf(s2), 1e-12f);
    float ha = y2a / n2, hb = y2b / n2;

    float ca = 0.6f * ga + 0.4f * ha, cb = 0.6f * gb + 0.4f * hb;
    float s3 = warp_sum(ca * ca + cb * cb);
    float n3 = fmaxf(sqrtf(s3), 1e-12f);
    float oa = ca / n3, ob = cb / n3;

    d_scratch[OFF_GN + (size_t)r * 64 + t]      = ga;
    d_scratch[OFF_GN + (size_t)r * 64 + t + 32] = gb;
    d_scratch[OFF_HN + (size_t)r * 64 + t]      = ha;
    d_scratch[OFF_HN + (size_t)r * 64 + t + 32] = hb;
    outp[(size_t)r * 64 + t]      = oa;
    outp[(size_t)r * 64 + t + 32] = ob;

    // log-softmax CE
    float mx = warp_max(fmaxf(oa, ob));
    float se = warp_sum(expf(oa - mx) + expf(ob - mx));
    float lse = mx + logf(se);

    float la = labels[(size_t)r * 64 + t], lb = labels[(size_t)r * 64 + t + 32];
    float sumLab = warp_sum(la + lb);
    float dotLO  = warp_sum(la * oa + lb * ob);

    float msum = d_scratch[OFF_ACC + A_MSK];
    float maskf = (float)mask[r] * ((float)N_ / msum);

    // argmax(outputs), argmax(labels) with first-index tie break
    float bv = oa; int bi = t;
    if (ob > bv) { bv = ob; bi = t + 32; }
    float lv = la; int li = t;
    if (lb > lv) { lv = lb; li = t + 32; }
#pragma unroll
    for (int o = 16; o; o >>= 1) {
        float vv = __shfl_xor_sync(0xffffffffu, bv, o);
        int   ii = __shfl_xor_sync(0xffffffffu, bi, o);
        if (vv > bv || (vv == bv && ii < bi)) { bv = vv; bi = ii; }
        float v2 = __shfl_xor_sync(0xffffffffu, lv, o);
        int   i2 = __shfl_xor_sync(0xffffffffu, li, o);
        if (v2 > lv || (v2 == lv && i2 < li)) { lv = v2; li = i2; }
    }

    // Wc dots & diag logit
    float wta = Wc[t], wtb = Wc[t + 32], wba = Wc[64 + t], wbb = Wc[96 + t];
    float u1 = warp_sum(ga * wta + gb * wtb);
    float v1 = warp_sum(ha * wba + hb * wbb);
    float u2 = warp_sum(ha * wta + hb * wtb);
    float v2 = warp_sum(ga * wba + gb * wbb);
    float dg = warp_sum(ga * ha + gb * hb);

    if (t == 0) {
        atomicAdd(&d_scratch[OFF_ACC + A_CE], maskf * (sumLab * lse - dotLO));
        atomicAdd(&d_scratch[OFF_ACC + A_ACCU], (bi == li) ? maskf : 0.f);
        d_scratch[OFF_U1 + r] = u1;
        d_scratch[OFF_V1 + r] = v1;
        d_scratch[OFF_U2 + r] = u2;
        d_scratch[OFF_V2 + r] = v2;
        d_scratch[OFF_DG + r] = 2.f * dg;   // dot / tau, tau = 0.5
    }
}

// ---------------------------------------------------------------------------
// edges: sum of log-sigmoid(z1), log-sigmoid(z2)
// ---------------------------------------------------------------------------
__global__ __launch_bounds__(256) void k_edges(const int* __restrict__ ei,
                                               const int* __restrict__ ej,
                                               const float* __restrict__ bcp) {
    __shared__ float sh[8];
    float bc = bcp[0];
    float s1 = 0.f, s2 = 0.f;
    for (int i = blockIdx.x * blockDim.x + threadIdx.x; i < E_;
         i += gridDim.x * blockDim.x) {
        int a = ei[i], b = ej[i];
        float z1 = d_scratch[OFF_U1 + a] + d_scratch[OFF_V1 + b] + bc;
        float z2 = d_scratch[OFF_U2 + a] + d_scratch[OFF_V2 + b] + bc;
        s1 += fminf(z1, 0.f) - log1pf(expf(-fabsf(z1)));
        s2 += fminf(z2, 0.f) - log1pf(expf(-fabsf(z2)));
    }
    block_atomic_add(s1, &d_scratch[OFF_ACC + A_LS1], sh);
    block_atomic_add(s2, &d_scratch[OFF_ACC + A_LS2], sh);
}

// ---------------------------------------------------------------------------
// N x N contrastive: row/col sums of exp(2 * GN @ HN^T), 64x64 tiles
// ---------------------------------------------------------------------------
__global__ __launch_bounds__(256) void k_contra_tile() {
    __shared__ float Gk[64][68];   // [k][i]
    __shared__ float Hk[64][68];   // [k][j]
    __shared__ float srow[64], scol[64];
    const int tid = threadIdx.x;
    const int i0 = blockIdx.y * 64, j0 = blockIdx.x * 64;
    const float* GN = d_scratch + OFF_GN;
    const float* HN = d_scratch + OFF_HN;

#pragma unroll
    for (int l = 0; l < 4; l++) {
        int f4 = tid + l * 256;
        int r = f4 >> 4, c4 = (f4 & 15) << 2;
        float4 g = *(const float4*)(GN + (size_t)(i0 + r) * 64 + c4);
        Gk[c4 + 0][r] = g.x; Gk[c4 + 1][r] = g.y;
        Gk[c4 + 2][r] = g.z; Gk[c4 + 3][r] = g.w;
        float4 h = *(const float4*)(HN + (size_t)(j0 + r) * 64 + c4);
        Hk[c4 + 0][r] = h.x; Hk[c4 + 1][r] = h.y;
        Hk[c4 + 2][r] = h.z; Hk[c4 + 3][r] = h.w;
    }
    if (tid < 64) { srow[tid] = 0.f; scol[tid] = 0.f; }
    __syncthreads();

    const int tr = tid >> 4, tc = tid & 15;
    float acc[4][4];
#pragma unroll
    for (int i = 0; i < 4; i++)
#pragma unroll
        for (int j = 0; j < 4; j++) acc[i][j] = 0.f;

#pragma unroll 8
    for (int k = 0; k < 64; k++) {
        float4 a4 = *(const float4*)&Gk[k][tr << 2];
        float4 b4 = *(const float4*)&Hk[k][tc << 2];
        float aa[4] = {a4.x, a4.y, a4.z, a4.w};
        float bb[4] = {b4.x, b4.y, b4.z, b4.w};
#pragma unroll
        for (int i = 0; i < 4; i++)
#pragma unroll
            for (int j = 0; j < 4; j++) acc[i][j] = fmaf(aa[i], bb[j], acc[i][j]);
    }

    float rp[4] = {0, 0, 0, 0}, cp[4] = {0, 0, 0, 0};
#pragma unroll
    for (int i = 0; i < 4; i++)
#pragma unroll
        for (int j = 0; j < 4; j++) {
            float e = __expf(2.f * acc[i][j]);
            rp[i] += e; cp[j] += e;
        }
#pragma unroll
    for (int i = 0; i < 4; i++) atomicAdd(&srow[(tr << 2) + i], rp[i]);
#pragma unroll
    for (int j = 0; j < 4; j++) atomicAdd(&scol[(tc << 2) + j], cp[j]);
    __syncthreads();
    if (tid < 64) {
        atomicAdd(&d_scratch[OFF_RE + i0 + tid], srow[tid]);
        atomicAdd(&d_scratch[OFF_CEc + j0 + tid], scol[tid]);
    }
}

__global__ __launch_bounds__(256) void k_contra_red() {
    __shared__ float sh[8];
    int i = blockIdx.x * blockDim.x + threadIdx.x;
    float v = 0.f;
    if (i < N_) {
        float ld = d_scratch[OFF_DG + i];
        v = (ld - logf(d_scratch[OFF_RE + i])) +
            (ld - logf(d_scratch[OFF_CEc + i])) + 2.f * logf((float)N_);
    }
    block_atomic_add(v, &d_scratch[OFF_ACC + A_CON], sh);
}

// ---------------------------------------------------------------------------
// supervised contrastive
// ---------------------------------------------------------------------------
__global__ __launch_bounds__(64) void k_gather(const int* __restrict__ tidx) {
    int b = blockIdx.x, t = threadIdx.x;
    int s = tidx[b];
    d_scratch[OFF_G1 + (size_t)b * 64 + t] = d_scratch[OFF_GN + (size_t)s * 64 + t];
    d_scratch[OFF_G2 + (size_t)b * 64 + t] = d_scratch[OFF_HN + (size_t)s * 64 + t];
}

__global__ __launch_bounds__(256) void k_rsa(const float* __restrict__ intra) {
    __shared__ float sh[8];
    int r = blockIdx.x;
    float v = 0.f;
    for (int j = threadIdx.x; j < M_; j += 256) v += intra[(size_t)r * M_ + j];
    int lane = threadIdx.x & 31, wid = threadIdx.x >> 5;
    v = warp_sum(v);
    if (lane == 0) sh[wid] = v;
    __syncthreads();
    if (wid == 0) {
        float x = (lane < 8) ? sh[lane] : 0.f;
        x = warp_sum(x);
        if (lane == 0) d_scratch[OFF_RSA + r] = x;
    }
}

__global__ __launch_bounds__(256) void k_sup_tile(const float* __restrict__ intra,
                                                  const float* __restrict__ inter) {
    __shared__ float Gk[64][68];   // [k][i]  (G1 rows i0..)
    __shared__ float Hk[64][68];   // [k][j]  (G2 rows j0..)
    __shared__ float s_r1[64], s_r2[64], s_c1[64], s_c2[64];
    const int tid = threadIdx.x;
    const int i0 = blockIdx.y * 64, j0 = blockIdx.x * 64;
    const float* G1 = d_scratch + OFF_G1;
    const float* G2 = d_scratch + OFF_G2;

#pragma unroll
    for (int l = 0; l < 4; l++) {
        int f4 = tid + l * 256;
        int r = f4 >> 4, c4 = (f4 & 15) << 2;
        float4 g = *(const float4*)(G1 + (size_t)(i0 + r) * 64 + c4);
        Gk[c4 + 0][r] = g.x; Gk[c4 + 1][r] = g.y;
        Gk[c4 + 2][r] = g.z; Gk[c4 + 3][r] = g.w;
        float4 h = *(const float4*)(G2 + (size_t)(j0 + r) * 64 + c4);
        Hk[c4 + 0][r] = h.x; Hk[c4 + 1][r] = h.y;
        Hk[c4 + 2][r] = h.z; Hk[c4 + 3][r] = h.w;
    }
    if (tid < 64) { s_r1[tid] = 0.f; s_r2[tid] = 0.f; s_c1[tid] = 0.f; s_c2[tid] = 0.f; }
    __syncthreads();

    const int tr = tid >> 4, tc = tid & 15;
    float acc[4][4];
#pragma unroll
    for (int i = 0; i < 4; i++)
#pragma unroll
        for (int j = 0; j < 4; j++) acc[i][j] = 0.f;

#pragma unroll 8
    for (int k = 0; k < 64; k++) {
        float4 a4 = *(const float4*)&Gk[k][tr << 2];
        float4 b4 = *(const float4*)&Hk[k][tc << 2];
        float aa[4] = {a4.x, a4.y, a4.z, a4.w};
        float bb[4] = {b4.x, b4.y, b4.z, b4.w};
#pragma unroll
        for (int i = 0; i < 4; i++)
#pragma unroll
            for (int j = 0; j < 4; j++) acc[i][j] = fmaf(aa[i], bb[j], acc[i][j]);
    }
    // exponentiate in place: hc1[i,j]
#pragma unroll
    for (int i = 0; i < 4; i++)
#pragma unroll
        for (int j = 0; j < 4; j++) acc[i][j] = __expf(2.f * acc[i][j]);

    // row direction (sup(h1t,h2t)): weights intra[i,j], inter[i,j]
#pragma unroll
    for (int ii = 0; ii < 4; ii++) {
        int gi = i0 + (tr << 2) + ii;
        const float4 wa = *(const float4*)(intra + (size_t)gi * M_ + j0 + (tc << 2));
        const float4 wb = *(const float4*)(inter + (size_t)gi * M_ + j0 + (tc << 2));
        float rs = acc[ii][0] * wa.x + acc[ii][1] * wa.y + acc[ii][2] * wa.z + acc[ii][3] * wa.w;
        float rn = acc[ii][0] * wb.x + acc[ii][1] * wb.y + acc[ii][2] * wb.z + acc[ii][3] * wb.w;
        atomicAdd(&s_r1[(tr << 2) + ii], rs);
        atomicAdd(&s_r2[(tr << 2) + ii], rn);
    }
    // col direction (sup(h2t,h1t)): hc2[j,i] = hc1[i,j]; weights intra[j,i], inter[j,i]
#pragma unroll
    for (int jj = 0; jj < 4; jj++) {
        int gj = j0 + (tc << 2) + jj;
        const float4 wa = *(const float4*)(intra + (size_t)gj * M_ + i0 + (tr << 2));
        const float4 wb = *(const float4*)(inter + (size_t)gj * M_ + i0 + (tr << 2));
        float cs = acc[0][jj] * wa.x + acc[1][jj] * wa.y + acc[2][jj] * wa.z + acc[3][jj] * wa.w;
        float cn = acc[0][jj] * wb.x + acc[1][jj] * wb.y + acc[2][jj] * wb.z + acc[3][jj] * wb.w;
        atomicAdd(&s_c1[(tc << 2) + jj], cs);
        atomicAdd(&s_c2[(tc << 2) + jj], cn);
    }
    __syncthreads();
    if (tid < 64) {
        atomicAdd(&d_scratch[OFF_SP1 + i0 + tid], s_r1[tid]);
        atomicAdd(&d_scratch[OFF_SN1 + i0 + tid], s_r2[tid]);
        atomicAdd(&d_scratch[OFF_SP2 + j0 + tid], s_c1[tid]);
        atomicAdd(&d_scratch[OFF_SN2 + j0 + tid], s_c2[tid]);
    }
}

__global__ __launch_bounds__(256) void k_sup_red() {
    __shared__ float sh[8];
    int i = blockIdx.x * blockDim.x + threadIdx.x;
    float v = 0.f;
    if (i < M_) {
        float lM = logf((float)(M_ - 1));
        float lr = logf(d_scratch[OFF_RSA + i]);
        float sp1 = d_scratch[OFF_SP1 + i], sn1 = d_scratch[OFF_SN1 + i];
        float sp2 = d_scratch[OFF_SP2 + i], sn2 = d_scratch[OFF_SN2 + i];
        v = (logf(sp1) - lr - logf(sn1 + sp1) + lM) +
            (logf(sp2) - lr - logf(sn2 + sp2) + lM);
    }
    block_atomic_add(v, &d_scratch[OFF_ACC + A_SUP], sh);
}

// ---------------------------------------------------------------------------
// weight decay
// ---------------------------------------------------------------------------
__global__ __launch_bounds__(256) void k_wd(const float* __restrict__ W0,
                                            const float* __restrict__ b0,
                                            const float* __restrict__ W1,
                                            const float* __restrict__ b1,
                                            const float* __restrict__ Wc,
                                            const float* __restrict__ bc) {
    __shared__ float sh[8];
    float v = 0.f;
    const int total = 65536 + 256 + 16384 + 64 + 128 + 1;  // 82369
    for (int idx = blockIdx.x * blockDim.x + threadIdx.x; idx < total;
         idx += gridDim.x * blockDim.x) {
        float x;
        if (idx < 65536)      x = W0[idx];
        else if (idx < 65792) x = b0[idx - 65536];
        else if (idx < 82176) x = W1[idx - 65792];
        else if (idx < 82240) x = b1[idx - 82176];
        else if (idx < 82368) x = Wc[idx - 82240];
        else                  x = bc[0];
        v += x * x;
    }
    block_atomic_add(v, &d_scratch[OFF_ACC + A_WDS], sh);
}

// ---------------------------------------------------------------------------
// finalize: loss & accuracy
// ---------------------------------------------------------------------------
__global__ void k_final(float* __restrict__ outp) {
    float lossce = d_scratch[OFF_ACC + A_CE] / (float)N_;
    float pe = -(d_scratch[OFF_ACC + A_LS1] + d_scratch[OFF_ACC + A_LS2]) / (float)E_;
    float con = -0.9f * (d_scratch[OFF_ACC + A_CON] / (2.f * (float)N_));
    float sup = -0.9f * (d_scratch[OFF_ACC + A_SUP] / (2.f * (float)M_));
    float wd  = 5e-4f * 0.5f * d_scratch[OFF_ACC + A_WDS];
    outp[(size_t)N_ * C_]     = lossce + 0.4f * pe + con + sup + wd;
    outp[(size_t)N_ * C_ + 1] = d_scratch[OFF_ACC + A_ACCU] / (float)N_;
}

// ---------------------------------------------------------------------------
// launch
// ---------------------------------------------------------------------------
extern "C" void kernel_launch(void* const* d_in, const int* in_sizes, int n_in,
                              void* d_out, int out_size) {
    const float* features = (const float*)d_in[0];
    const float* support  = (const float*)d_in[1];
    const float* labels   = (const float*)d_in[2];
    const float* intra    = (const float*)d_in[3];
    const float* inter    = (const float*)d_in[4];
    const float* W0  = (const float*)d_in[5];
    const float* b0  = (const float*)d_in[6];
    const float* W1  = (const float*)d_in[7];
    const float* b1  = (const float*)d_in[8];
    const float* Wh0 = (const float*)d_in[9];
    const float* bh0 = (const float*)d_in[10];
    const float* Wh1 = (const float*)d_in[11];
    const float* bh1 = (const float*)d_in[12];
    const float* Wc  = (const float*)d_in[13];
    const float* bc  = (const float*)d_in[14];
    const int* ei    = (const int*)d_in[15];
    const int* ej    = (const int*)d_in[16];
    const int* tidx  = (const int*)d_in[17];
    const int* mask  = (const int*)d_in[18];
    float* outp = (float*)d_out;

    float* scr = nullptr;
    cudaGetSymbolAddress((void**)&scr, d_scratch);

    // zero accumulators (inside the graph -> replays stay correct)
    k_zero<<<(2 * N_ + 255) / 256, 256>>>(scr + OFF_RE, 2 * N_);      // rowE + colE
    k_zero<<<(4 * M_ + 255) / 256, 256>>>(scr + OFF_SP1, 4 * M_);     // sp1..sn2
    k_zero<<<1, 64>>>(scr + OFF_ACC, 64);

    k_prep<<<256, 256>>>(W0, Wh0, b0, bh0, b1, bh1);
    k_masksum<<<32, 256>>>(mask);

    // XW = X @ [W0|Wh0]                 (8192x512, K=256)
    k_sgemm<<<dim3(8, 128), 256>>>(features, 256, scr + OFF_WCAT, 512,
                                   nullptr, scr + OFF_XW, 512, 256, 0);
    // H = relu(S @ XW + [b0|bh0])       (8192x512, K=8192)
    k_sgemm<<<dim3(8, 128), 256>>>(support, 8192, scr + OFF_XW, 512,
                                   scr + OFF_BCAT, scr + OFF_H, 512, 8192, 1);
    // HW[:, :64]  = h0 @ W1             (K=256)
    k_sgemm<<<dim3(1, 128), 256>>>(scr + OFF_H, 512, W1, 64,
                                   nullptr, scr + OFF_HW, 128, 256, 0);
    // HW[:, 64:]  = g0 @ Wh1
    k_sgemm<<<dim3(1, 128), 256>>>(scr + OFF_H + 256, 512, Wh1, 64,
                                   nullptr, scr + OFF_HW + 64, 128, 256, 0);
    // Y = S @ HW + [b1|bh1]             (8192x128, K=8192)
    k_sgemm<<<dim3(2, 128), 256>>>(support, 8192, scr + OFF_HW, 128,
                                   scr + OFF_BCAT2, scr + OFF_Y, 128, 8192, 0);

    k_rownorm<<<N_, 32>>>(labels, Wc, bc, mask, outp);
    k_edges<<<256, 256>>>(ei, ej, bc);

    k_contra_tile<<<dim3(128, 128), 256>>>();
    k_contra_red<<<32, 256>>>();

    k_gather<<<M_, 64>>>(tidx);
    k_rsa<<<M_, 256>>>(intra);
    k_sup_tile<<<dim3(32, 32), 256>>>(intra, inter);
    k_sup_red<<<8, 256>>>();

    k_wd<<<64, 256>>>(W0, b0, W1, b1, Wc, bc);
    k_final<<<1, 1>>>(outp);
}

// round 3
// speedup vs baseline: 1.7947x; 1.7947x over previous
#include <cuda_runtime.h>
#include <cuda_bf16.h>
#include <math.h>
#include <stdint.h>

// ---------------------------------------------------------------------------
// Problem constants
// ---------------------------------------------------------------------------
namespace {
constexpr int N_ = 8192;
constexpr int C_ = 64;
constexpr int E_ = 262144;
constexpr int M_ = 2048;

// accumulator slots
enum { A_CE = 0, A_ACCU, A_LS1, A_LS2, A_CON, A_SUP, A_WDS, A_MSK };

// scratch layout (floats)
constexpr size_t OFF_XWT  = 0;                                 // 512 x 8192
constexpr size_t OFF_H    = OFF_XWT  + (size_t)512 * 8192;     // 8192 x 512
constexpr size_t OFF_HWT  = OFF_H    + (size_t)N_ * 512;       // 128 x 8192
constexpr size_t OFF_Y    = OFF_HWT  + (size_t)128 * 8192;     // 8192 x 128
constexpr size_t OFF_GN   = OFF_Y    + (size_t)N_ * 128;       // 8192 x 64
constexpr size_t OFF_HN   = OFF_GN   + (size_t)N_ * 64;        // 8192 x 64
constexpr size_t OFF_WCT  = OFF_HN   + (size_t)N_ * 64;        // 512 x 256
constexpr size_t OFF_BBLK = OFF_WCT  + 512 * 256;              // 128 x 512
constexpr size_t OFF_BCAT = OFF_BBLK + 128 * 512;              // 512
constexpr size_t OFF_BCAT2= OFF_BCAT + 512;                    // 128
constexpr size_t OFF_U1   = OFF_BCAT2 + 128;                   // N
constexpr size_t OFF_V1   = OFF_U1 + N_;
constexpr size_t OFF_U2   = OFF_V1 + N_;
constexpr size_t OFF_V2   = OFF_U2 + N_;
constexpr size_t OFF_DG   = OFF_V2 + N_;                       // diag logits
constexpr size_t OFF_RE   = OFF_DG + N_;                       // row sums exp
constexpr size_t OFF_CEc  = OFF_RE + N_;                       // col sums exp
constexpr size_t OFF_G1   = OFF_CEc + N_;                      // 2048 x 64
constexpr size_t OFF_G2   = OFF_G1 + (size_t)M_ * 64;          // 2048 x 64
constexpr size_t OFF_SP1  = OFF_G2 + (size_t)M_ * 64;          // M
constexpr size_t OFF_SN1  = OFF_SP1 + M_;
constexpr size_t OFF_SP2  = OFF_SN1 + M_;
constexpr size_t OFF_SN2  = OFF_SP2 + M_;
constexpr size_t OFF_RSA  = OFF_SN2 + M_;
constexpr size_t OFF_ACC  = OFF_RSA + M_;                      // 64 scalars
constexpr size_t SCR_TOT  = OFF_ACC + 64;
}  // namespace

__device__ __align__(256) float d_scratch[SCR_TOT];

// ---------------------------------------------------------------------------
// reduction helpers
// ---------------------------------------------------------------------------
__device__ __forceinline__ float warp_sum(float v) {
#pragma unroll
    for (int o = 16; o; o >>= 1) v += __shfl_xor_sync(0xffffffffu, v, o);
    return v;
}
__device__ __forceinline__ float warp_max(float v) {
#pragma unroll
    for (int o = 16; o; o >>= 1) v = fmaxf(v, __shfl_xor_sync(0xffffffffu, v, o));
    return v;
}
__device__ __forceinline__ void block_atomic_add(float v, float* dst, float* shbuf) {
    int lane = threadIdx.x & 31, wid = threadIdx.x >> 5;
    v = warp_sum(v);
    if (lane == 0) shbuf[wid] = v;
    __syncthreads();
    if (wid == 0) {
        float x = (lane < (int)(blockDim.x >> 5)) ? shbuf[lane] : 0.f;
        x = warp_sum(x);
        if (lane == 0) atomicAdd(dst, x);
    }
    __syncthreads();
}

// ---------------------------------------------------------------------------
// mma.sync wrapper: D += A(16x16) * B(16x8), bf16 in, fp32 acc
// ---------------------------------------------------------------------------
__device__ __forceinline__ void mma16816(float* c, const uint32_t* a, const uint32_t* b) {
    asm volatile(
        "mma.sync.aligned.m16n8k16.row.col.f32.bf16.bf16.f32 "
        "{%0,%1,%2,%3}, {%4,%5,%6,%7}, {%8,%9}, {%0,%1,%2,%3};"
        : "+f"(c[0]), "+f"(c[1]), "+f"(c[2]), "+f"(c[3])
        : "r"(a[0]), "r"(a[1]), "r"(a[2]), "r"(a[3]), "r"(b[0]), "r"(b[1]));
}

// split one float4 into hi/lo bf16 pairs and store as uint2 at byte ptrs
__device__ __forceinline__ void split_store(float4 v, char* hp, char* lp) {
    __nv_bfloat16 h0 = __float2bfloat16(v.x);
    __nv_bfloat16 h1 = __float2bfloat16(v.y);
    __nv_bfloat16 h2 = __float2bfloat16(v.z);
    __nv_bfloat16 h3 = __float2bfloat16(v.w);
    uint2 hh;
    hh.x = (uint32_t)__bfloat16_as_ushort(h0) | ((uint32_t)__bfloat16_as_ushort(h1) << 16);
    hh.y = (uint32_t)__bfloat16_as_ushort(h2) | ((uint32_t)__bfloat16_as_ushort(h3) << 16);
    *reinterpret_cast<uint2*>(hp) = hh;
    __nv_bfloat16 l0 = __float2bfloat16(v.x - __bfloat162float(h0));
    __nv_bfloat16 l1 = __float2bfloat16(v.y - __bfloat162float(h1));
    __nv_bfloat16 l2 = __float2bfloat16(v.z - __bfloat162float(h2));
    __nv_bfloat16 l3 = __float2bfloat16(v.w - __bfloat162float(h3));
    uint2 ll;
    ll.x = (uint32_t)__bfloat16_as_ushort(l0) | ((uint32_t)__bfloat16_as_ushort(l1) << 16);
    ll.y = (uint32_t)__bfloat16_as_ushort(l2) | ((uint32_t)__bfloat16_as_ushort(l3) << 16);
    *reinterpret_cast<uint2*>(lp) = ll;
}

// ---------------------------------------------------------------------------
// split-bf16 HMMA GEMM: C[MT x 128] tile of A[M,K] @ B[N,K]^T  (fp32 in/out)
// 3 passes: Ah*Bh + Ah*Bl + Al*Bh.  flags: bit0=relu, bit1=transposed output.
// 256 threads; warp grid 2(m) x 4(n); warp tile (MT/2) x 32.
// ---------------------------------------------------------------------------
template <int MT>
__global__ __launch_bounds__(256) void k_hgemm(
    const float* __restrict__ A, int lda,
    const float* __restrict__ B, int ldb,
    const float* __restrict__ bias,
    float* __restrict__ C, int ldc,
    int K, int flags)
{
    constexpr int SK = 40;                         // padded k-stride (elements)
    constexpr int ASZ = MT * SK;                   // elements per A component
    constexpr int BSZ = 128 * SK;
    constexpr int BUFE = 2 * ASZ + 2 * BSZ;        // elements per buffer
    constexpr int MFRAG = MT / 32;                 // m16 frags per warp

    extern __shared__ __nv_bfloat16 sm[];
    const int tid = threadIdx.x, w = tid >> 5, lane = tid & 31;
    const int m0 = blockIdx.y * MT, n0 = blockIdx.x * 128;

    const int wm0 = (w >> 2) * (MT / 2);           // warp m offset (local)
    const int wn0 = (w & 3) * 32;                  // warp n offset (local)

    const int lrow = tid >> 3;                     // loader row 0..31
    const int lk4  = (tid & 7) << 2;               // loader k 0..28

    float acc[MFRAG][4][4];
#pragma unroll
    for (int i = 0; i < MFRAG; i++)
#pragma unroll
        for (int j = 0; j < 4; j++)
#pragma unroll
            for (int q = 0; q < 4; q++) acc[i][j][q] = 0.f;

    const int NC = K >> 5;
    float4 pA[MT / 32], pB[4];

    // direct load of chunk 0
    {
        char* ah = (char*)(sm);
        char* al = (char*)(sm + ASZ);
        char* bh = (char*)(sm + 2 * ASZ);
        char* bl = (char*)(sm + 2 * ASZ + BSZ);
#pragma unroll
        for (int i = 0; i < MT / 32; i++) {
            int r = lrow + i * 32;
            float4 v = *(const float4*)(A + (size_t)(m0 + r) * lda + lk4);
            int off2 = (r * SK + lk4) * 2;
            split_store(v, ah + off2, al + off2);
        }
#pragma unroll
        for (int i = 0; i < 4; i++) {
            int r = lrow + i * 32;
            float4 v = *(const float4*)(B + (size_t)(n0 + r) * ldb + lk4);
            int off2 = (r * SK + lk4) * 2;
            split_store(v, bh + off2, bl + off2);
        }
    }

    const int fr = lane >> 2;                      // 0..7
    const int fk = (lane & 3) << 1;                // 0,2,4,6

    for (int c = 0; c < NC; c++) {
        __syncthreads();
        // prefetch next chunk into registers
        if (c + 1 < NC) {
            int k0 = (c + 1) << 5;
#pragma unroll
            for (int i = 0; i < MT / 32; i++)
                pA[i] = *(const float4*)(A + (size_t)(m0 + lrow + i * 32) * lda + k0 + lk4);
#pragma unroll
            for (int i = 0; i < 4; i++)
                pB[i] = *(const float4*)(B + (size_t)(n0 + lrow + i * 32) * ldb + k0 + lk4);
        }

        // compute on buffer c&1
        const uint32_t* Ah32 = (const uint32_t*)(sm + (size_t)(c & 1) * BUFE);
        const uint32_t* Al32 = Ah32 + ASZ / 2;
        const uint32_t* Bh32 = Al32 + ASZ / 2;
        const uint32_t* Bl32 = Bh32 + BSZ / 2;

#pragma unroll
        for (int ks = 0; ks < 2; ks++) {
            const int kb = ks * 16;
            uint32_t af_h[MFRAG][4], af_l[MFRAG][4], bf_h[4][2], bf_l[4][2];
#pragma unroll
            for (int mi = 0; mi < MFRAG; mi++) {
                int r = wm0 + mi * 16 + fr;
                int kk = kb + fk;
                af_h[mi][0] = Ah32[r * (SK / 2) + (kk >> 1)];
                af_h[mi][1] = Ah32[(r + 8) * (SK / 2) + (kk >> 1)];
                af_h[mi][2] = Ah32[r * (SK / 2) + ((kk + 8) >> 1)];
                af_h[mi][3] = Ah32[(r + 8) * (SK / 2) + ((kk + 8) >> 1)];
                af_l[mi][0] = Al32[r * (SK / 2) + (kk >> 1)];
                af_l[mi][1] = Al32[(r + 8) * (SK / 2) + (kk >> 1)];
                af_l[mi][2] = Al32[r * (SK / 2) + ((kk + 8) >> 1)];
                af_l[mi][3] = Al32[(r + 8) * (SK / 2) + ((kk + 8) >> 1)];
            }
#pragma unroll
            for (int ni = 0; ni < 4; ni++) {
                int n = wn0 + ni * 8 + fr;
                int kk = kb + fk;
                bf_h[ni][0] = Bh32[n * (SK / 2) + (kk >> 1)];
                bf_h[ni][1] = Bh32[n * (SK / 2) + ((kk + 8) >> 1)];
                bf_l[ni][0] = Bl32[n * (SK / 2) + (kk >> 1)];
                bf_l[ni][1] = Bl32[n * (SK / 2) + ((kk + 8) >> 1)];
            }
#pragma unroll
            for (int mi = 0; mi < MFRAG; mi++)
#pragma unroll
                for (int ni = 0; ni < 4; ni++) {
                    mma16816(acc[mi][ni], af_h[mi], bf_h[ni]);
                    mma16816(acc[mi][ni], af_h[mi], bf_l[ni]);
                    mma16816(acc[mi][ni], af_l[mi], bf_h[ni]);
                }
        }

        // store prefetched chunk into other buffer
        if (c + 1 < NC) {
            char* nb = (char*)(sm + (size_t)((c + 1) & 1) * BUFE);
            char* ah = nb;
            char* al = nb + ASZ * 2;
            char* bh = nb + 4 * ASZ;
            char* bl = nb + 4 * ASZ + BSZ * 2;
#pragma unroll
            for (int i = 0; i < MT / 32; i++) {
                int off2 = ((lrow + i * 32) * SK + lk4) * 2;
                split_store(pA[i], ah + off2, al + off2);
            }
#pragma unroll
            for (int i = 0; i < 4; i++) {
                int off2 = ((lrow + i * 32) * SK + lk4) * 2;
                split_store(pB[i], bh + off2, bl + off2);
            }
        }
    }

    // epilogue
    const bool relu  = (flags & 1) != 0;
    const bool trans = (flags & 2) != 0;
#pragma unroll
    for (int mi = 0; mi < MFRAG; mi++) {
#pragma unroll
        for (int ni = 0; ni < 4; ni++) {
            int gr = m0 + wm0 + mi * 16 + fr;
            int gc = n0 + wn0 + ni * 8 + fk;
            float v0 = acc[mi][ni][0], v1 = acc[mi][ni][1];
            float v2 = acc[mi][ni][2], v3 = acc[mi][ni][3];
            if (trans) {
                C[(size_t)gc * ldc + gr]           = v0;
                C[(size_t)(gc + 1) * ldc + gr]     = v1;
                C[(size_t)gc * ldc + gr + 8]       = v2;
                C[(size_t)(gc + 1) * ldc + gr + 8] = v3;
            } else {
                if (bias) {
                    float b0 = bias[gc], b1 = bias[gc + 1];
                    v0 += b0; v1 += b1; v2 += b0; v3 += b1;
                }
                if (relu) {
                    v0 = fmaxf(v0, 0.f); v1 = fmaxf(v1, 0.f);
                    v2 = fmaxf(v2, 0.f); v3 = fmaxf(v3, 0.f);
                }
                *(float2*)(C + (size_t)gr * ldc + gc)       = make_float2(v0, v1);
                *(float2*)(C + (size_t)(gr + 8) * ldc + gc) = make_float2(v2, v3);
            }
        }
    }
}

// ---------------------------------------------------------------------------
// utility kernels
// ---------------------------------------------------------------------------
__global__ void k_zero(float* p, int n) {
    int i = blockIdx.x * blockDim.x + threadIdx.x;
    if (i < n) p[i] = 0.f;
}

__global__ void k_prep(const float* __restrict__ W0, const float* __restrict__ Wh0,
                       const float* __restrict__ W1, const float* __restrict__ Wh1,
                       const float* __restrict__ b0, const float* __restrict__ bh0,
                       const float* __restrict__ b1, const float* __restrict__ bh1) {
    int i = blockIdx.x * blockDim.x + threadIdx.x;
    if (i < 512 * 256) {   // WcatT[n][k]
        int n = i >> 8, k = i & 255;
        d_scratch[OFF_WCT + i] = (n < 256) ? W0[k * 256 + n] : Wh0[k * 256 + (n - 256)];
    }
    if (i < 128 * 512) {   // Bblk[n][k] block diagonal
        int n = i >> 9, k = i & 511;
        float v = 0.f;
        if (n < 64) { if (k < 256) v = W1[k * 64 + n]; }
        else        { if (k >= 256) v = Wh1[(k - 256) * 64 + (n - 64)]; }
        d_scratch[OFF_BBLK + i] = v;
    }
    if (i < 256) {
        d_scratch[OFF_BCAT + i]       = b0[i];
        d_scratch[OFF_BCAT + 256 + i] = bh0[i];
    }
    if (i < 64) {
        d_scratch[OFF_BCAT2 + i]      = b1[i];
        d_scratch[OFF_BCAT2 + 64 + i] = bh1[i];
    }
}

__global__ void k_masksum(const int* __restrict__ mask) {
    __shared__ float sh[8];
    int i = blockIdx.x * blockDim.x + threadIdx.x;
    float v = (i < N_) ? (float)mask[i] : 0.f;
    block_atomic_add(v, &d_scratch[OFF_ACC + A_MSK], sh);
}

// ---------------------------------------------------------------------------
// per-row: l2norms, outputs, CE, accuracy, Wc dots, diag logits
// ---------------------------------------------------------------------------
__global__ __launch_bounds__(32) void k_rownorm(
    const float* __restrict__ labels, const float* __restrict__ Wc,
    const float* __restrict__ bcp, const int* __restrict__ mask,
    float* __restrict__ outp)
{
    const int r = blockIdx.x;
    const int t = threadIdx.x;
    const float* Y = d_scratch + OFF_Y + (size_t)r * 128;

    float y1a = Y[t],      y1b = Y[t + 32];
    float y2a = Y[64 + t], y2b = Y[96 + t];

    float s1 = warp_sum(y1a * y1a + y1b * y1b);
    float n1 = fmaxf(sqrtf(s1), 1e-12f);
    float ga = y1a / n1, gb = y1b / n1;

    float s2 = warp_sum(y2a * y2a + y2b * y2b);
    float n2 = fmaxf(sqrtf(s2), 1e-12f);
    float ha = y2a / n2, hb = y2b / n2;

    float ca = 0.6f * ga + 0.4f * ha, cb = 0.6f * gb + 0.4f * hb;
    float s3 = warp_sum(ca * ca + cb * cb);
    float n3 = fmaxf(sqrtf(s3), 1e-12f);
    float oa = ca / n3, ob = cb / n3;

    d_scratch[OFF_GN + (size_t)r * 64 + t]      = ga;
    d_scratch[OFF_GN + (size_t)r * 64 + t + 32] = gb;
    d_scratch[OFF_HN + (size_t)r * 64 + t]      = ha;
    d_scratch[OFF_HN + (size_t)r * 64 + t + 32] = hb;
    outp[(size_t)r * 64 + t]      = oa;
    outp[(size_t)r * 64 + t + 32] = ob;

    float mx = warp_max(fmaxf(oa, ob));
    float se = warp_sum(expf(oa - mx) + expf(ob - mx));
    float lse = mx + logf(se);

    float la = labels[(size_t)r * 64 + t], lb = labels[(size_t)r * 64 + t + 32];
    float sumLab = warp_sum(la + lb);
    float dotLO  = warp_sum(la * oa + lb * ob);

    float msum = d_scratch[OFF_ACC + A_MSK];
    float maskf = (float)mask[r] * ((float)N_ / msum);

    float bv = oa; int bi = t;
    if (ob > bv) { bv = ob; bi = t + 32; }
    float lv = la; int li = t;
    if (lb > lv) { lv = lb; li = t + 32; }
#pragma unroll
    for (int o = 16; o; o >>= 1) {
        float vv = __shfl_xor_sync(0xffffffffu, bv, o);
        int   ii = __shfl_xor_sync(0xffffffffu, bi, o);
        if (vv > bv || (vv == bv && ii < bi)) { bv = vv; bi = ii; }
        float v2 = __shfl_xor_sync(0xffffffffu, lv, o);
        int   i2 = __shfl_xor_sync(0xffffffffu, li, o);
        if (v2 > lv || (v2 == lv && i2 < li)) { lv = v2; li = i2; }
    }

    float wta = Wc[t], wtb = Wc[t + 32], wba = Wc[64 + t], wbb = Wc[96 + t];
    float u1 = warp_sum(ga * wta + gb * wtb);
    float v1 = warp_sum(ha * wba + hb * wbb);
    float u2 = warp_sum(ha * wta + hb * wtb);
    float v2 = warp_sum(ga * wba + gb * wbb);
    float dg = warp_sum(ga * ha + gb * hb);

    if (t == 0) {
        atomicAdd(&d_scratch[OFF_ACC + A_CE], maskf * (sumLab * lse - dotLO));
        atomicAdd(&d_scratch[OFF_ACC + A_ACCU], (bi == li) ? maskf : 0.f);
        d_scratch[OFF_U1 + r] = u1;
        d_scratch[OFF_V1 + r] = v1;
        d_scratch[OFF_U2 + r] = u2;
        d_scratch[OFF_V2 + r] = v2;
        d_scratch[OFF_DG + r] = 2.f * dg;
    }
}

// ---------------------------------------------------------------------------
// edges
// ---------------------------------------------------------------------------
__global__ __launch_bounds__(256) void k_edges(const int* __restrict__ ei,
                                               const int* __restrict__ ej,
                                               const float* __restrict__ bcp) {
    __shared__ float sh[8];
    float bc = bcp[0];
    float s1 = 0.f, s2 = 0.f;
    for (int i = blockIdx.x * blockDim.x + threadIdx.x; i < E_;
         i += gridDim.x * blockDim.x) {
        int a = ei[i], b = ej[i];
        float z1 = d_scratch[OFF_U1 + a] + d_scratch[OFF_V1 + b] + bc;
        float z2 = d_scratch[OFF_U2 + a] + d_scratch[OFF_V2 + b] + bc;
        s1 += fminf(z1, 0.f) - log1pf(expf(-fabsf(z1)));
        s2 += fminf(z2, 0.f) - log1pf(expf(-fabsf(z2)));
    }
    block_atomic_add(s1, &d_scratch[OFF_ACC + A_LS1], sh);
    block_atomic_add(s2, &d_scratch[OFF_ACC + A_LS2], sh);
}

// ---------------------------------------------------------------------------
// N x N contrastive: row/col sums of exp(2 * GN @ HN^T)
// ---------------------------------------------------------------------------
__global__ __launch_bounds__(256) void k_contra_tile() {
    __shared__ float Gk[64][68];
    __shared__ float Hk[64][68];
    __shared__ float srow[64], scol[64];
    const int tid = threadIdx.x;
    const int i0 = blockIdx.y * 64, j0 = blockIdx.x * 64;
    const float* GN = d_scratch + OFF_GN;
    const float* HN = d_scratch + OFF_HN;

#pragma unroll
    for (int l = 0; l < 4; l++) {
        int f4 = tid + l * 256;
        int r = f4 >> 4, c4 = (f4 & 15) << 2;
        float4 g = *(const float4*)(GN + (size_t)(i0 + r) * 64 + c4);
        Gk[c4 + 0][r] = g.x; Gk[c4 + 1][r] = g.y;
        Gk[c4 + 2][r] = g.z; Gk[c4 + 3][r] = g.w;
        float4 h = *(const float4*)(HN + (size_t)(j0 + r) * 64 + c4);
        Hk[c4 + 0][r] = h.x; Hk[c4 + 1][r] = h.y;
        Hk[c4 + 2][r] = h.z; Hk[c4 + 3][r] = h.w;
    }
    if (tid < 64) { srow[tid] = 0.f; scol[tid] = 0.f; }
    __syncthreads();

    const int tr = tid >> 4, tc = tid & 15;
    float acc[4][4];
#pragma unroll
    for (int i = 0; i < 4; i++)
#pragma unroll
        for (int j = 0; j < 4; j++) acc[i][j] = 0.f;

#pragma unroll 8
    for (int k = 0; k < 64; k++) {
        float4 a4 = *(const float4*)&Gk[k][tr << 2];
        float4 b4 = *(const float4*)&Hk[k][tc << 2];
        float aa[4] = {a4.x, a4.y, a4.z, a4.w};
        float bb[4] = {b4.x, b4.y, b4.z, b4.w};
#pragma unroll
        for (int i = 0; i < 4; i++)
#pragma unroll
            for (int j = 0; j < 4; j++) acc[i][j] = fmaf(aa[i], bb[j], acc[i][j]);
    }

    float rp[4] = {0, 0, 0, 0}, cp[4] = {0, 0, 0, 0};
#pragma unroll
    for (int i = 0; i < 4; i++)
#pragma unroll
        for (int j = 0; j < 4; j++) {
            float e = __expf(2.f * acc[i][j]);
            rp[i] += e; cp[j] += e;
        }
#pragma unroll
    for (int i = 0; i < 4; i++) atomicAdd(&srow[(tr << 2) + i], rp[i]);
#pragma unroll
    for (int j = 0; j < 4; j++) atomicAdd(&scol[(tc << 2) + j], cp[j]);
    __syncthreads();
    if (tid < 64) {
        atomicAdd(&d_scratch[OFF_RE + i0 + tid], srow[tid]);
        atomicAdd(&d_scratch[OFF_CEc + j0 + tid], scol[tid]);
    }
}

__global__ __launch_bounds__(256) void k_contra_red() {
    __shared__ float sh[8];
    int i = blockIdx.x * blockDim.x + threadIdx.x;
    float v = 0.f;
    if (i < N_) {
        float ld = d_scratch[OFF_DG + i];
        v = (ld - logf(d_scratch[OFF_RE + i])) +
            (ld - logf(d_scratch[OFF_CEc + i])) + 2.f * logf((float)N_);
    }
    block_atomic_add(v, &d_scratch[OFF_ACC + A_CON], sh);
}

// ---------------------------------------------------------------------------
// supervised contrastive
// ---------------------------------------------------------------------------
__global__ __launch_bounds__(64) void k_gather(const int* __restrict__ tidx) {
    int b = blockIdx.x, t = threadIdx.x;
    int s = tidx[b];
    d_scratch[OFF_G1 + (size_t)b * 64 + t] = d_scratch[OFF_GN + (size_t)s * 64 + t];
    d_scratch[OFF_G2 + (size_t)b * 64 + t] = d_scratch[OFF_HN + (size_t)s * 64 + t];
}

__global__ __launch_bounds__(256) void k_rsa(const float* __restrict__ intra) {
    __shared__ float sh[8];
    int r = blockIdx.x;
    float v = 0.f;
    for (int j = threadIdx.x; j < M_; j += 256) v += intra[(size_t)r * M_ + j];
    int lane = threadIdx.x & 31, wid = threadIdx.x >> 5;
    v = warp_sum(v);
    if (lane == 0) sh[wid] = v;
    __syncthreads();
    if (wid == 0) {
        float x = (lane < 8) ? sh[lane] : 0.f;
        x = warp_sum(x);
        if (lane == 0) d_scratch[OFF_RSA + r] = x;
    }
}

__global__ __launch_bounds__(256) void k_sup_tile(const float* __restrict__ intra,
                                                  const float* __restrict__ inter) {
    __shared__ float Gk[64][68];
    __shared__ float Hk[64][68];
    __shared__ float s_r1[64], s_r2[64], s_c1[64], s_c2[64];
    const int tid = threadIdx.x;
    const int i0 = blockIdx.y * 64, j0 = blockIdx.x * 64;
    const float* G1 = d_scratch + OFF_G1;
    const float* G2 = d_scratch + OFF_G2;

#pragma unroll
    for (int l = 0; l < 4; l++) {
        int f4 = tid + l * 256;
        int r = f4 >> 4, c4 = (f4 & 15) << 2;
        float4 g = *(const float4*)(G1 + (size_t)(i0 + r) * 64 + c4);
        Gk[c4 + 0][r] = g.x; Gk[c4 + 1][r] = g.y;
        Gk[c4 + 2][r] = g.z; Gk[c4 + 3][r] = g.w;
        float4 h = *(const float4*)(G2 + (size_t)(j0 + r) * 64 + c4);
        Hk[c4 + 0][r] = h.x; Hk[c4 + 1][r] = h.y;
        Hk[c4 + 2][r] = h.z; Hk[c4 + 3][r] = h.w;
    }
    if (tid < 64) { s_r1[tid] = 0.f; s_r2[tid] = 0.f; s_c1[tid] = 0.f; s_c2[tid] = 0.f; }
    __syncthreads();

    const int tr = tid >> 4, tc = tid & 15;
    float acc[4][4];
#pragma unroll
    for (int i = 0; i < 4; i++)
#pragma unroll
        for (int j = 0; j < 4; j++) acc[i][j] = 0.f;

#pragma unroll 8
    for (int k = 0; k < 64; k++) {
        float4 a4 = *(const float4*)&Gk[k][tr << 2];
        float4 b4 = *(const float4*)&Hk[k][tc << 2];
        float aa[4] = {a4.x, a4.y, a4.z, a4.w};
        float bb[4] = {b4.x, b4.y, b4.z, b4.w};
#pragma unroll
        for (int i = 0; i < 4; i++)
#pragma unroll
            for (int j = 0; j < 4; j++) acc[i][j] = fmaf(aa[i], bb[j], acc[i][j]);
    }
#pragma unroll
    for (int i = 0; i < 4; i++)
#pragma unroll
        for (int j = 0; j < 4; j++) acc[i][j] = __expf(2.f * acc[i][j]);

#pragma unroll
    for (int ii = 0; ii < 4; ii++) {
        int gi = i0 + (tr << 2) + ii;
        const float4 wa = *(const float4*)(intra + (size_t)gi * M_ + j0 + (tc << 2));
        const float4 wb = *(const float4*)(inter + (size_t)gi * M_ + j0 + (tc << 2));
        float rs = acc[ii][0] * wa.x + acc[ii][1] * wa.y + acc[ii][2] * wa.z + acc[ii][3] * wa.w;
        float rn = acc[ii][0] * wb.x + acc[ii][1] * wb.y + acc[ii][2] * wb.z + acc[ii][3] * wb.w;
        atomicAdd(&s_r1[(tr << 2) + ii], rs);
        atomicAdd(&s_r2[(tr << 2) + ii], rn);
    }
#pragma unroll
    for (int jj = 0; jj < 4; jj++) {
        int gj = j0 + (tc << 2) + jj;
        const float4 wa = *(const float4*)(intra + (size_t)gj * M_ + i0 + (tr << 2));
        const float4 wb = *(const float4*)(inter + (size_t)gj * M_ + i0 + (tr << 2));
        float cs = acc[0][jj] * wa.x + acc[1][jj] * wa.y + acc[2][jj] * wa.z + acc[3][jj] * wa.w;
        float cn = acc[0][jj] * wb.x + acc[1][jj] * wb.y + acc[2][jj] * wb.z + acc[3][jj] * wb.w;
        atomicAdd(&s_c1[(tc << 2) + jj], cs);
        atomicAdd(&s_c2[(tc << 2) + jj], cn);
    }
    __syncthreads();
    if (tid < 64) {
        atomicAdd(&d_scratch[OFF_SP1 + i0 + tid], s_r1[tid]);
        atomicAdd(&d_scratch[OFF_SN1 + i0 + tid], s_r2[tid]);
        atomicAdd(&d_scratch[OFF_SP2 + j0 + tid], s_c1[tid]);
        atomicAdd(&d_scratch[OFF_SN2 + j0 + tid], s_c2[tid]);
    }
}

__global__ __launch_bounds__(256) void k_sup_red() {
    __shared__ float sh[8];
    int i = blockIdx.x * blockDim.x + threadIdx.x;
    float v = 0.f;
    if (i < M_) {
        float lM = logf((float)(M_ - 1));
        float lr = logf(d_scratch[OFF_RSA + i]);
        float sp1 = d_scratch[OFF_SP1 + i], sn1 = d_scratch[OFF_SN1 + i];
        float sp2 = d_scratch[OFF_SP2 + i], sn2 = d_scratch[OFF_SN2 + i];
        v = (logf(sp1) - lr - logf(sn1 + sp1) + lM) +
            (logf(sp2) - lr - logf(sn2 + sp2) + lM);
    }
    block_atomic_add(v, &d_scratch[OFF_ACC + A_SUP], sh);
}

// ---------------------------------------------------------------------------
// weight decay
// ---------------------------------------------------------------------------
__global__ __launch_bounds__(256) void k_wd(const float* __restrict__ W0,
                                            const float* __restrict__ b0,
                                            const float* __restrict__ W1,
                                            const float* __restrict__ b1,
                                            const float* __restrict__ Wc,
                                            const float* __restrict__ bc) {
    __shared__ float sh[8];
    float v = 0.f;
    const int total = 65536 + 256 + 16384 + 64 + 128 + 1;
    for (int idx = blockIdx.x * blockDim.x + threadIdx.x; idx < total;
         idx += gridDim.x * blockDim.x) {
        float x;
        if (idx < 65536)      x = W0[idx];
        else if (idx < 65792) x = b0[idx - 65536];
        else if (idx < 82176) x = W1[idx - 65792];
        else if (idx < 82240) x = b1[idx - 82176];
        else if (idx < 82368) x = Wc[idx - 82240];
        else                  x = bc[0];
        v += x * x;
    }
    block_atomic_add(v, &d_scratch[OFF_ACC + A_WDS], sh);
}

// ---------------------------------------------------------------------------
// finalize
// ---------------------------------------------------------------------------
__global__ void k_final(float* __restrict__ outp) {
    float lossce = d_scratch[OFF_ACC + A_CE] / (float)N_;
    float pe = -(d_scratch[OFF_ACC + A_LS1] + d_scratch[OFF_ACC + A_LS2]) / (float)E_;
    float con = -0.9f * (d_scratch[OFF_ACC + A_CON] / (2.f * (float)N_));
    float sup = -0.9f * (d_scratch[OFF_ACC + A_SUP] / (2.f * (float)M_));
    float wd  = 5e-4f * 0.5f * d_scratch[OFF_ACC + A_WDS];
    outp[(size_t)N_ * C_]     = lossce + 0.4f * pe + con + sup + wd;
    outp[(size_t)N_ * C_ + 1] = d_scratch[OFF_ACC + A_ACCU] / (float)N_;
}

// ---------------------------------------------------------------------------
// launch
// ---------------------------------------------------------------------------
extern "C" void kernel_launch(void* const* d_in, const int* in_sizes, int n_in,
                              void* d_out, int out_size) {
    const float* features = (const float*)d_in[0];
    const float* support  = (const float*)d_in[1];
    const float* labels   = (const float*)d_in[2];
    const float* intra    = (const float*)d_in[3];
    const float* inter    = (const float*)d_in[4];
    const float* W0  = (const float*)d_in[5];
    const float* b0  = (const float*)d_in[6];
    const float* W1  = (const float*)d_in[7];
    const float* b1  = (const float*)d_in[8];
    const float* Wh0 = (const float*)d_in[9];
    const float* bh0 = (const float*)d_in[10];
    const float* Wh1 = (const float*)d_in[11];
    const float* bh1 = (const float*)d_in[12];
    const float* Wc  = (const float*)d_in[13];
    const float* bc  = (const float*)d_in[14];
    const int* ei    = (const int*)d_in[15];
    const int* ej    = (const int*)d_in[16];
    const int* tidx  = (const int*)d_in[17];
    const int* mask  = (const int*)d_in[18];
    float* outp = (float*)d_out;

    float* scr = nullptr;
    cudaGetSymbolAddress((void**)&scr, d_scratch);

    // dynamic smem: double buffer of (2*A + 2*B) bf16 tiles, padded stride 40
    constexpr int SMEM128 = 2 * (2 * 128 * 40 + 2 * 128 * 40) * 2;  // 81920
    constexpr int SMEM64  = 2 * (2 * 64 * 40 + 2 * 128 * 40) * 2;   // 61440
    cudaFuncSetAttribute(k_hgemm<128>, cudaFuncAttributeMaxDynamicSharedMemorySize, SMEM128);
    cudaFuncSetAttribute(k_hgemm<64>,  cudaFuncAttributeMaxDynamicSharedMemorySize, SMEM64);

    // zero accumulators (inside graph)
    k_zero<<<(2 * N_ + 255) / 256, 256>>>(scr + OFF_RE, 2 * N_);
    k_zero<<<(4 * M_ + 255) / 256, 256>>>(scr + OFF_SP1, 4 * M_);
    k_zero<<<1, 64>>>(scr + OFF_ACC, 64);

    k_prep<<<512, 256>>>(W0, Wh0, W1, Wh1, b0, bh0, b1, bh1);
    k_masksum<<<32, 256>>>(mask);

    // G1: XWt[512,8192] = (X @ Wcat)^T    A=X[8192,256], B=WcatT[512,256]
    k_hgemm<128><<<dim3(4, 64), 256, SMEM128>>>(
        features, 256, scr + OFF_WCT, 256, nullptr,
        scr + OFF_XWT, 8192, 256, /*trans*/2);

    // G2: H[8192,512] = relu(S @ XW + bcat)    A=S, B=XWt[512,8192]
    k_hgemm<128><<<dim3(4, 64), 256, SMEM128>>>(
        support, 8192, scr + OFF_XWT, 8192, scr + OFF_BCAT,
        scr + OFF_H, 512, 8192, /*relu*/1);

    // G3: HWt[128,8192] = (H @ Bblk^T)^T    A=H[8192,512], B=Bblk[128,512]
    k_hgemm<128><<<dim3(1, 64), 256, SMEM128>>>(
        scr + OFF_H, 512, scr + OFF_BBLK, 512, nullptr,
        scr + OFF_HWT, 8192, 512, /*trans*/2);

    // G4: Y[8192,128] = S @ HW + bcat2    A=S, B=HWt[128,8192]  (MT=64 fills chip)
    k_hgemm<64><<<dim3(1, 128), 256, SMEM64>>>(
        support, 8192, scr + OFF_HWT, 8192, scr + OFF_BCAT2,
        scr + OFF_Y, 128, 8192, 0);

    k_rownorm<<<N_, 32>>>(labels, Wc, bc, mask, outp);
    k_edges<<<256, 256>>>(ei, ej, bc);

    k_contra_tile<<<dim3(128, 128), 256>>>();
    k_contra_red<<<32, 256>>>();

    k_gather<<<M_, 64>>>(tidx);
    k_rsa<<<M_, 256>>>(intra);
    k_sup_tile<<<dim3(32, 32), 256>>>(intra, inter);
    k_sup_red<<<8, 256>>>();

    k_wd<<<64, 256>>>(W0, b0, W1, b1, Wc, bc);
    k_final<<<1, 1>>>(outp);
}

// round 4
// speedup vs baseline: 2.4369x; 1.3579x over previous
#include <cuda_runtime.h>
#include <cuda_bf16.h>
#include <math.h>
#include <stdint.h>

// ---------------------------------------------------------------------------
// Problem constants
// ---------------------------------------------------------------------------
namespace {
constexpr int N_ = 8192;
constexpr int C_ = 64;
constexpr int E_ = 262144;
constexpr int M_ = 2048;

enum { A_CE = 0, A_ACCU, A_LS1, A_LS2, A_CON, A_SUP, A_WDS, A_MSK };

// fp32 scratch layout
constexpr size_t OFF_Y    = 0;                                 // 8192 x 128
constexpr size_t OFF_GN   = OFF_Y    + (size_t)N_ * 128;       // 8192 x 64
constexpr size_t OFF_HN   = OFF_GN   + (size_t)N_ * 64;        // 8192 x 64
constexpr size_t OFF_BCAT = OFF_HN   + (size_t)N_ * 64;        // 512
constexpr size_t OFF_BCAT2= OFF_BCAT + 512;                    // 128
constexpr size_t OFF_U1   = OFF_BCAT2 + 128;                   // N
constexpr size_t OFF_V1   = OFF_U1 + N_;
constexpr size_t OFF_U2   = OFF_V1 + N_;
constexpr size_t OFF_V2   = OFF_U2 + N_;
constexpr size_t OFF_DG   = OFF_V2 + N_;
constexpr size_t OFF_RE   = OFF_DG + N_;
constexpr size_t OFF_CEc  = OFF_RE + N_;
constexpr size_t OFF_G1   = OFF_CEc + N_;                      // 2048 x 64
constexpr size_t OFF_G2   = OFF_G1 + (size_t)M_ * 64;          // 2048 x 64
constexpr size_t OFF_SP1  = OFF_G2 + (size_t)M_ * 64;
constexpr size_t OFF_SN1  = OFF_SP1 + M_;
constexpr size_t OFF_SP2  = OFF_SN1 + M_;
constexpr size_t OFF_SN2  = OFF_SP2 + M_;
constexpr size_t OFF_RSA  = OFF_SN2 + M_;
constexpr size_t OFF_ACC  = OFF_RSA + M_;                      // 64 scalars
constexpr size_t SCR_TOT  = OFF_ACC + 64;
}  // namespace

__device__ __align__(256) float d_scratch[SCR_TOT];

// bf16 split-pair operand arrays
__device__ __align__(256) __nv_bfloat16 d_Sh[(size_t)N_ * N_];
__device__ __align__(256) __nv_bfloat16 d_Sl[(size_t)N_ * N_];
__device__ __align__(256) __nv_bfloat16 d_Xh[(size_t)N_ * 256];
__device__ __align__(256) __nv_bfloat16 d_Xl[(size_t)N_ * 256];
__device__ __align__(256) __nv_bfloat16 d_Wch[512 * 256], d_Wcl[512 * 256];
__device__ __align__(256) __nv_bfloat16 d_Bbh[128 * 512], d_Bbl[128 * 512];
__device__ __align__(256) __nv_bfloat16 d_XWh[(size_t)512 * N_], d_XWl[(size_t)512 * N_];
__device__ __align__(256) __nv_bfloat16 d_Hh[(size_t)N_ * 512], d_Hl[(size_t)N_ * 512];
__device__ __align__(256) __nv_bfloat16 d_HWh[(size_t)128 * N_], d_HWl[(size_t)128 * N_];
__device__ __align__(256) __nv_bfloat16 d_GNh[(size_t)N_ * 64], d_GNl[(size_t)N_ * 64];
__device__ __align__(256) __nv_bfloat16 d_HNh[(size_t)N_ * 64], d_HNl[(size_t)N_ * 64];

// ---------------------------------------------------------------------------
// helpers
// ---------------------------------------------------------------------------
__device__ __forceinline__ float warp_sum(float v) {
#pragma unroll
    for (int o = 16; o; o >>= 1) v += __shfl_xor_sync(0xffffffffu, v, o);
    return v;
}
__device__ __forceinline__ float warp_max(float v) {
#pragma unroll
    for (int o = 16; o; o >>= 1) v = fmaxf(v, __shfl_xor_sync(0xffffffffu, v, o));
    return v;
}
__device__ __forceinline__ void block_atomic_add(float v, float* dst, float* shbuf) {
    int lane = threadIdx.x & 31, wid = threadIdx.x >> 5;
    v = warp_sum(v);
    if (lane == 0) shbuf[wid] = v;
    __syncthreads();
    if (wid == 0) {
        float x = (lane < (int)(blockDim.x >> 5)) ? shbuf[lane] : 0.f;
        x = warp_sum(x);
        if (lane == 0) atomicAdd(dst, x);
    }
    __syncthreads();
}

__device__ __forceinline__ uint32_t smem_to_u32(const void* p) {
    uint32_t a;
    asm("{ .reg .u64 t; cvta.to.shared.u64 t, %1; cvt.u32.u64 %0, t; }"
        : "=r"(a) : "l"(p));
    return a;
}
__device__ __forceinline__ void cp_async16(uint32_t dst, const void* src) {
    asm volatile("cp.async.cg.shared.global [%0], [%1], 16;" :: "r"(dst), "l"(src));
}
__device__ __forceinline__ void cp_commit() {
    asm volatile("cp.async.commit_group;" ::: "memory");
}
template <int Nn>
__device__ __forceinline__ void cp_wait() {
    asm volatile("cp.async.wait_group %0;" :: "n"(Nn) : "memory");
}

__device__ __forceinline__ void mma16816(float* c, const uint32_t* a, const uint32_t* b) {
    asm volatile(
        "mma.sync.aligned.m16n8k16.row.col.f32.bf16.bf16.f32 "
        "{%0,%1,%2,%3}, {%4,%5,%6,%7}, {%8,%9}, {%0,%1,%2,%3};"
        : "+f"(c[0]), "+f"(c[1]), "+f"(c[2]), "+f"(c[3])
        : "r"(a[0]), "r"(a[1]), "r"(a[2]), "r"(a[3]), "r"(b[0]), "r"(b[1]));
}

__device__ __forceinline__ void split1(float v, __nv_bfloat16& h, __nv_bfloat16& l) {
    h = __float2bfloat16(v);
    l = __float2bfloat16(v - __bfloat162float(h));
}
__device__ __forceinline__ void split_store4(float4 v, char* hp, char* lp) {
    __nv_bfloat16 h0, h1, h2, h3, l0, l1, l2, l3;
    split1(v.x, h0, l0); split1(v.y, h1, l1);
    split1(v.z, h2, l2); split1(v.w, h3, l3);
    uint2 hh, ll;
    hh.x = (uint32_t)__bfloat16_as_ushort(h0) | ((uint32_t)__bfloat16_as_ushort(h1) << 16);
    hh.y = (uint32_t)__bfloat16_as_ushort(h2) | ((uint32_t)__bfloat16_as_ushort(h3) << 16);
    ll.x = (uint32_t)__bfloat16_as_ushort(l0) | ((uint32_t)__bfloat16_as_ushort(l1) << 16);
    ll.y = (uint32_t)__bfloat16_as_ushort(l2) | ((uint32_t)__bfloat16_as_ushort(l3) << 16);
    *reinterpret_cast<uint2*>(hp) = hh;
    *reinterpret_cast<uint2*>(lp) = ll;
}
__device__ __forceinline__ uint32_t pack_bf2(float a, float b) {
    return (uint32_t)__bfloat16_as_ushort(__float2bfloat16(a)) |
           ((uint32_t)__bfloat16_as_ushort(__float2bfloat16(b)) << 16);
}

// ---------------------------------------------------------------------------
// split kernel: fp32 -> (hi, lo) bf16 arrays
// ---------------------------------------------------------------------------
__global__ void k_split(const float* __restrict__ src,
                        __nv_bfloat16* __restrict__ hi,
                        __nv_bfloat16* __restrict__ lo, size_t n4) {
    size_t i = (size_t)blockIdx.x * blockDim.x + threadIdx.x;
    size_t stride = (size_t)gridDim.x * blockDim.x;
    for (; i < n4; i += stride) {
        float4 v = reinterpret_cast<const float4*>(src)[i];
        split_store4(v, (char*)(hi + i * 4), (char*)(lo + i * 4));
    }
}

// ---------------------------------------------------------------------------
// cp.async pipelined split-bf16 HMMA GEMM
// C[MT x NT] tile of A[M,K] @ B[N,K]^T, inputs pre-split bf16 pairs
// flags: 1=relu, 2=transposed output, 4=pair (bf16 hi/lo) output
// ---------------------------------------------------------------------------
template <int MT, int NT, int STAGES>
__global__ __launch_bounds__(256) void k_bgemm(
    const __nv_bfloat16* __restrict__ Ah, const __nv_bfloat16* __restrict__ Al, int lda,
    const __nv_bfloat16* __restrict__ Bh, const __nv_bfloat16* __restrict__ Bl, int ldb,
    const float* __restrict__ bias, float* __restrict__ Cf,
    __nv_bfloat16* __restrict__ Ch, __nv_bfloat16* __restrict__ Cl, int ldc,
    int K, int flags)
{
    constexpr int SK = 40;                      // padded elems per smem row
    constexpr int ASZ = MT * SK;
    constexpr int BSZ = NT * SK;
    constexpr int SE = 2 * ASZ + 2 * BSZ;       // elems per stage
    constexpr int MFRAG = MT / 32;
    constexpr int NFRAG = NT / 32;
    constexpr int AIT = (MT * 4) / 256;
    constexpr int BIT = (NT * 4) / 256;

    extern __shared__ __nv_bfloat16 sm[];
    const int tid = threadIdx.x, w = tid >> 5, lane = tid & 31;
    const int m0 = blockIdx.y * MT, n0 = blockIdx.x * NT;
    const int wm0 = (w >> 2) * (MT / 2);
    const int wn0 = (w & 3) * (NT / 4);
    const int fr = lane >> 2, fk = (lane & 3) << 1;
    const uint32_t sbase = smem_to_u32(sm);

    float acc[MFRAG][NFRAG][4];
#pragma unroll
    for (int i = 0; i < MFRAG; i++)
#pragma unroll
        for (int j = 0; j < NFRAG; j++)
#pragma unroll
            for (int q = 0; q < 4; q++) acc[i][j][q] = 0.f;

    const int NC = K >> 5;
    const int lrow = tid >> 2, lseg = tid & 3;

    auto issue = [&](int c) {
        const int s = c % STAGES;
        const int k0 = c << 5;
        const uint32_t st = sbase + (uint32_t)s * SE * 2;
#pragma unroll
        for (int i = 0; i < AIT; i++) {
            int row = lrow + i * 64;
            uint32_t d = st + (uint32_t)(row * SK + lseg * 8) * 2;
            size_t g = (size_t)(m0 + row) * lda + k0 + lseg * 8;
            cp_async16(d, Ah + g);
            cp_async16(d + ASZ * 2, Al + g);
        }
#pragma unroll
        for (int i = 0; i < BIT; i++) {
            int row = lrow + i * 64;
            uint32_t d = st + (uint32_t)(2 * ASZ + row * SK + lseg * 8) * 2;
            size_t g = (size_t)(n0 + row) * ldb + k0 + lseg * 8;
            cp_async16(d, Bh + g);
            cp_async16(d + BSZ * 2, Bl + g);
        }
        cp_commit();
    };

#pragma unroll
    for (int s = 0; s < STAGES - 1; s++) issue(s);

    for (int c = 0; c < NC; c++) {
        if (c + STAGES - 1 < NC) issue(c + STAGES - 1);
        else cp_commit();
        cp_wait<STAGES - 1>();
        __syncthreads();

        const uint32_t* A32h = (const uint32_t*)(sm + (size_t)(c % STAGES) * SE);
        const uint32_t* A32l = A32h + ASZ / 2;
        const uint32_t* B32h = A32l + ASZ / 2;
        const uint32_t* B32l = B32h + BSZ / 2;

#pragma unroll
        for (int ks = 0; ks < 2; ks++) {
            const int kw = (ks * 16 + fk) >> 1;
            uint32_t afh[MFRAG][4], afl[MFRAG][4];
#pragma unroll
            for (int mi = 0; mi < MFRAG; mi++) {
                int r = wm0 + mi * 16 + fr;
                afh[mi][0] = A32h[r * 20 + kw];
                afh[mi][1] = A32h[(r + 8) * 20 + kw];
                afh[mi][2] = A32h[r * 20 + kw + 4];
                afh[mi][3] = A32h[(r + 8) * 20 + kw + 4];
                afl[mi][0] = A32l[r * 20 + kw];
                afl[mi][1] = A32l[(r + 8) * 20 + kw];
                afl[mi][2] = A32l[r * 20 + kw + 4];
                afl[mi][3] = A32l[(r + 8) * 20 + kw + 4];
            }
#pragma unroll
            for (int ni = 0; ni < NFRAG; ni++) {
                int n = wn0 + ni * 8 + fr;
                uint32_t bh[2] = {B32h[n * 20 + kw], B32h[n * 20 + kw + 4]};
                uint32_t bl[2] = {B32l[n * 20 + kw], B32l[n * 20 + kw + 4]};
#pragma unroll
                for (int mi = 0; mi < MFRAG; mi++) {
                    mma16816(acc[mi][ni], afh[mi], bh);
                    mma16816(acc[mi][ni], afl[mi], bh);
                    mma16816(acc[mi][ni], afh[mi], bl);
                }
            }
        }
        __syncthreads();
    }

    const bool relu  = (flags & 1) != 0;
    const bool trans = (flags & 2) != 0;
    const bool pair  = (flags & 4) != 0;
#pragma unroll
    for (int mi = 0; mi < MFRAG; mi++) {
#pragma unroll
        for (int ni = 0; ni < NFRAG; ni++) {
            int gr = m0 + wm0 + mi * 16 + fr;
            int gc = n0 + wn0 + ni * 8 + fk;
            float v0 = acc[mi][ni][0], v1 = acc[mi][ni][1];
            float v2 = acc[mi][ni][2], v3 = acc[mi][ni][3];
            if (bias) {
                float b0 = bias[gc], b1 = bias[gc + 1];
                v0 += b0; v1 += b1; v2 += b0; v3 += b1;
            }
            if (relu) {
                v0 = fmaxf(v0, 0.f); v1 = fmaxf(v1, 0.f);
                v2 = fmaxf(v2, 0.f); v3 = fmaxf(v3, 0.f);
            }
            if (pair) {
                if (trans) {
                    __nv_bfloat16 h, l;
                    split1(v0, h, l);
                    Ch[(size_t)gc * ldc + gr] = h;       Cl[(size_t)gc * ldc + gr] = l;
                    split1(v1, h, l);
                    Ch[(size_t)(gc + 1) * ldc + gr] = h; Cl[(size_t)(gc + 1) * ldc + gr] = l;
                    split1(v2, h, l);
                    Ch[(size_t)gc * ldc + gr + 8] = h;   Cl[(size_t)gc * ldc + gr + 8] = l;
                    split1(v3, h, l);
                    Ch[(size_t)(gc + 1) * ldc + gr + 8] = h;
                    Cl[(size_t)(gc + 1) * ldc + gr + 8] = l;
                } else {
                    float r0 = __bfloat162float(__float2bfloat16(v0));
                    float r1 = __bfloat162float(__float2bfloat16(v1));
                    float r2 = __bfloat162float(__float2bfloat16(v2));
                    float r3 = __bfloat162float(__float2bfloat16(v3));
                    *(uint32_t*)(Ch + (size_t)gr * ldc + gc)       = pack_bf2(v0, v1);
                    *(uint32_t*)(Cl + (size_t)gr * ldc + gc)       = pack_bf2(v0 - r0, v1 - r1);
                    *(uint32_t*)(Ch + (size_t)(gr + 8) * ldc + gc) = pack_bf2(v2, v3);
                    *(uint32_t*)(Cl + (size_t)(gr + 8) * ldc + gc) = pack_bf2(v2 - r2, v3 - r3);
                }
            } else {
                *(float2*)(Cf + (size_t)gr * ldc + gc)       = make_float2(v0, v1);
                *(float2*)(Cf + (size_t)(gr + 8) * ldc + gc) = make_float2(v2, v3);
            }
        }
    }
}

// ---------------------------------------------------------------------------
// utility kernels
// ---------------------------------------------------------------------------
__global__ void k_zero(float* p, int n) {
    int i = blockIdx.x * blockDim.x + threadIdx.x;
    if (i < n) p[i] = 0.f;
}

__global__ void k_prep(const float* __restrict__ W0, const float* __restrict__ Wh0,
                       const float* __restrict__ W1, const float* __restrict__ Wh1,
                       const float* __restrict__ b0, const float* __restrict__ bh0,
                       const float* __restrict__ b1, const float* __restrict__ bh1) {
    int i = blockIdx.x * blockDim.x + threadIdx.x;
    if (i < 512 * 256) {   // WcatT[n][k]
        int n = i >> 8, k = i & 255;
        float v = (n < 256) ? W0[k * 256 + n] : Wh0[k * 256 + (n - 256)];
        split1(v, d_Wch[i], d_Wcl[i]);
    }
    if (i < 128 * 512) {   // Bblk[n][k] block diagonal
        int n = i >> 9, k = i & 511;
        float v = 0.f;
        if (n < 64) { if (k < 256) v = W1[k * 64 + n]; }
        else        { if (k >= 256) v = Wh1[(k - 256) * 64 + (n - 64)]; }
        split1(v, d_Bbh[i], d_Bbl[i]);
    }
    if (i < 256) {
        d_scratch[OFF_BCAT + i]       = b0[i];
        d_scratch[OFF_BCAT + 256 + i] = bh0[i];
    }
    if (i < 64) {
        d_scratch[OFF_BCAT2 + i]      = b1[i];
        d_scratch[OFF_BCAT2 + 64 + i] = bh1[i];
    }
}

__global__ void k_masksum(const int* __restrict__ mask) {
    __shared__ float sh[8];
    int i = blockIdx.x * blockDim.x + threadIdx.x;
    float v = (i < N_) ? (float)mask[i] : 0.f;
    block_atomic_add(v, &d_scratch[OFF_ACC + A_MSK], sh);
}

// ---------------------------------------------------------------------------
// per-row: l2norms, outputs, CE, accuracy, Wc dots, diag logits, bf16 pairs
// ---------------------------------------------------------------------------
__global__ __launch_bounds__(32) void k_rownorm(
    const float* __restrict__ labels, const float* __restrict__ Wc,
    const float* __restrict__ bcp, const int* __restrict__ mask,
    float* __restrict__ outp)
{
    const int r = blockIdx.x;
    const int t = threadIdx.x;
    const float* Y = d_scratch + OFF_Y + (size_t)r * 128;

    float y1a = Y[t],      y1b = Y[t + 32];
    float y2a = Y[64 + t], y2b = Y[96 + t];

    float s1 = warp_sum(y1a * y1a + y1b * y1b);
    float n1 = fmaxf(sqrtf(s1), 1e-12f);
    float ga = y1a / n1, gb = y1b / n1;

    float s2 = warp_sum(y2a * y2a + y2b * y2b);
    float n2 = fmaxf(sqrtf(s2), 1e-12f);
    float ha = y2a / n2, hb = y2b / n2;

    float ca = 0.6f * ga + 0.4f * ha, cb = 0.6f * gb + 0.4f * hb;
    float s3 = warp_sum(ca * ca + cb * cb);
    float n3 = fmaxf(sqrtf(s3), 1e-12f);
    float oa = ca / n3, ob = cb / n3;

    d_scratch[OFF_GN + (size_t)r * 64 + t]      = ga;
    d_scratch[OFF_GN + (size_t)r * 64 + t + 32] = gb;
    d_scratch[OFF_HN + (size_t)r * 64 + t]      = ha;
    d_scratch[OFF_HN + (size_t)r * 64 + t + 32] = hb;
    split1(ga, d_GNh[(size_t)r * 64 + t],      d_GNl[(size_t)r * 64 + t]);
    split1(gb, d_GNh[(size_t)r * 64 + t + 32], d_GNl[(size_t)r * 64 + t + 32]);
    split1(ha, d_HNh[(size_t)r * 64 + t],      d_HNl[(size_t)r * 64 + t]);
    split1(hb, d_HNh[(size_t)r * 64 + t + 32], d_HNl[(size_t)r * 64 + t + 32]);
    outp[(size_t)r * 64 + t]      = oa;
    outp[(size_t)r * 64 + t + 32] = ob;

    float mx = warp_max(fmaxf(oa, ob));
    float se = warp_sum(expf(oa - mx) + expf(ob - mx));
    float lse = mx + logf(se);

    float la = labels[(size_t)r * 64 + t], lb = labels[(size_t)r * 64 + t + 32];
    float sumLab = warp_sum(la + lb);
    float dotLO  = warp_sum(la * oa + lb * ob);

    float msum = d_scratch[OFF_ACC + A_MSK];
    float maskf = (float)mask[r] * ((float)N_ / msum);

    float bv = oa; int bi = t;
    if (ob > bv) { bv = ob; bi = t + 32; }
    float lv = la; int li = t;
    if (lb > lv) { lv = lb; li = t + 32; }
#pragma unroll
    for (int o = 16; o; o >>= 1) {
        float vv = __shfl_xor_sync(0xffffffffu, bv, o);
        int   ii = __shfl_xor_sync(0xffffffffu, bi, o);
        if (vv > bv || (vv == bv && ii < bi)) { bv = vv; bi = ii; }
        float v2 = __shfl_xor_sync(0xffffffffu, lv, o);
        int   i2 = __shfl_xor_sync(0xffffffffu, li, o);
        if (v2 > lv || (v2 == lv && i2 < li)) { lv = v2; li = i2; }
    }

    float wta = Wc[t], wtb = Wc[t + 32], wba = Wc[64 + t], wbb = Wc[96 + t];
    float u1 = warp_sum(ga * wta + gb * wtb);
    float v1 = warp_sum(ha * wba + hb * wbb);
    float u2 = warp_sum(ha * wta + hb * wtb);
    float v2 = warp_sum(ga * wba + gb * wbb);
    float dg = warp_sum(ga * ha + gb * hb);

    if (t == 0) {
        atomicAdd(&d_scratch[OFF_ACC + A_CE], maskf * (sumLab * lse - dotLO));
        atomicAdd(&d_scratch[OFF_ACC + A_ACCU], (bi == li) ? maskf : 0.f);
        d_scratch[OFF_U1 + r] = u1;
        d_scratch[OFF_V1 + r] = v1;
        d_scratch[OFF_U2 + r] = u2;
        d_scratch[OFF_V2 + r] = v2;
        d_scratch[OFF_DG + r] = 2.f * dg;
    }
}

// ---------------------------------------------------------------------------
// edges
// ---------------------------------------------------------------------------
__global__ __launch_bounds__(256) void k_edges(const int* __restrict__ ei,
                                               const int* __restrict__ ej,
                                               const float* __restrict__ bcp) {
    __shared__ float sh[8];
    float bc = bcp[0];
    float s1 = 0.f, s2 = 0.f;
    for (int i = blockIdx.x * blockDim.x + threadIdx.x; i < E_;
         i += gridDim.x * blockDim.x) {
        int a = ei[i], b = ej[i];
        float z1 = d_scratch[OFF_U1 + a] + d_scratch[OFF_V1 + b] + bc;
        float z2 = d_scratch[OFF_U2 + a] + d_scratch[OFF_V2 + b] + bc;
        s1 += fminf(z1, 0.f) - log1pf(expf(-fabsf(z1)));
        s2 += fminf(z2, 0.f) - log1pf(expf(-fabsf(z2)));
    }
    block_atomic_add(s1, &d_scratch[OFF_ACC + A_LS1], sh);
    block_atomic_add(s2, &d_scratch[OFF_ACC + A_LS2], sh);
}

// ---------------------------------------------------------------------------
// N x N contrastive, HMMA logits: row/col sums of exp(2 * GN @ HN^T)
// 128x128 tile per block, 256 threads, warp tile 64x32
// ---------------------------------------------------------------------------
__global__ __launch_bounds__(256) void k_contra_mma() {
    constexpr int SK2 = 72;                      // padded elems per row
    constexpr int CSZ = 128 * SK2;               // elems per component
    extern __shared__ __nv_bfloat16 cm[];
    __shared__ float srow[128], scol[128];

    const int tid = threadIdx.x, w = tid >> 5, lane = tid & 31;
    const int i0 = blockIdx.y * 128, j0 = blockIdx.x * 128;
    const int wm0 = (w >> 2) * 64, wn0 = (w & 3) * 32;
    const int fr = lane >> 2, fk = (lane & 3) << 1;

    // load tiles: 128 rows x 64 cols, 8 segs of 16B per row, per component
    const int lrow = tid >> 1, lseg = tid & 1;   // 2 segs of 4x16B? -> use 8 segs mapping
    {
        // 128 rows * 8 segs = 1024 units per component; 4 iters of 256
#pragma unroll
        for (int i = 0; i < 4; i++) {
            int idx = tid + (i << 8);
            int row = idx >> 3, seg = idx & 7;
            size_t g = (size_t)(i0 + row) * 64 + seg * 8;
            size_t g2 = (size_t)(j0 + row) * 64 + seg * 8;
            uint32_t off = (uint32_t)(row * SK2 + seg * 8);
            *(uint4*)((char*)cm + (size_t)off * 2)                 = *(const uint4*)(d_GNh + g);
            *(uint4*)((char*)cm + ((size_t)off + CSZ) * 2)         = *(const uint4*)(d_GNl + g);
            *(uint4*)((char*)cm + ((size_t)off + 2 * CSZ) * 2)     = *(const uint4*)(d_HNh + g2);
            *(uint4*)((char*)cm + ((size_t)off + 3 * CSZ) * 2)     = *(const uint4*)(d_HNl + g2);
        }
    }
    if (tid < 128) { srow[tid] = 0.f; scol[tid] = 0.f; }
    __syncthreads();

    float acc[4][4][4];
#pragma unroll
    for (int i = 0; i < 4; i++)
#pragma unroll
        for (int j = 0; j < 4; j++)
#pragma unroll
            for (int q = 0; q < 4; q++) acc[i][j][q] = 0.f;

    const uint32_t* A32h = (const uint32_t*)cm;
    const uint32_t* A32l = A32h + CSZ / 2;
    const uint32_t* B32h = A32l + CSZ / 2;
    const uint32_t* B32l = B32h + CSZ / 2;

#pragma unroll
    for (int ks = 0; ks < 4; ks++) {
        const int kw = (ks * 16 + fk) >> 1;
        uint32_t afh[4][4], afl[4][4];
#pragma unroll
        for (int mi = 0; mi < 4; mi++) {
            int r = wm0 + mi * 16 + fr;
            afh[mi][0] = A32h[r * 36 + kw];
            afh[mi][1] = A32h[(r + 8) * 36 + kw];
            afh[mi][2] = A32h[r * 36 + kw + 4];
            afh[mi][3] = A32h[(r + 8) * 36 + kw + 4];
            afl[mi][0] = A32l[r * 36 + kw];
            afl[mi][1] = A32l[(r + 8) * 36 + kw];
            afl[mi][2] = A32l[r * 36 + kw + 4];
            afl[mi][3] = A32l[(r + 8) * 36 + kw + 4];
        }
#pragma unroll
        for (int ni = 0; ni < 4; ni++) {
            int n = wn0 + ni * 8 + fr;
            uint32_t bh[2] = {B32h[n * 36 + kw], B32h[n * 36 + kw + 4]};
            uint32_t bl[2] = {B32l[n * 36 + kw], B32l[n * 36 + kw + 4]};
#pragma unroll
            for (int mi = 0; mi < 4; mi++) {
                mma16816(acc[mi][ni], afh[mi], bh);
                mma16816(acc[mi][ni], afl[mi], bh);
                mma16816(acc[mi][ni], afh[mi], bl);
            }
        }
    }

    // exp + row/col partial sums
    float rq[4][2] = {}, cq[4][2] = {};
#pragma unroll
    for (int mi = 0; mi < 4; mi++)
#pragma unroll
        for (int ni = 0; ni < 4; ni++) {
            float e0 = __expf(2.f * acc[mi][ni][0]);
            float e1 = __expf(2.f * acc[mi][ni][1]);
            float e2 = __expf(2.f * acc[mi][ni][2]);
            float e3 = __expf(2.f * acc[mi][ni][3]);
            rq[mi][0] += e0 + e1; rq[mi][1] += e2 + e3;
            cq[ni][0] += e0 + e2; cq[ni][1] += e1 + e3;
        }
#pragma unroll
    for (int mi = 0; mi < 4; mi++)
#pragma unroll
        for (int x = 0; x < 2; x++) {
            float v = rq[mi][x];
            v += __shfl_xor_sync(0xffffffffu, v, 1);
            v += __shfl_xor_sync(0xffffffffu, v, 2);
            if ((lane & 3) == 0) atomicAdd(&srow[wm0 + mi * 16 + fr + x * 8], v);
        }
#pragma unroll
    for (int ni = 0; ni < 4; ni++)
#pragma unroll
        for (int x = 0; x < 2; x++) {
            float v = cq[ni][x];
            v += __shfl_xor_sync(0xffffffffu, v, 4);
            v += __shfl_xor_sync(0xffffffffu, v, 8);
            v += __shfl_xor_sync(0xffffffffu, v, 16);
            if (lane < 4) atomicAdd(&scol[wn0 + ni * 8 + fk + x], v);
        }
    __syncthreads();
    if (tid < 128) {
        atomicAdd(&d_scratch[OFF_RE + i0 + tid], srow[tid]);
        atomicAdd(&d_scratch[OFF_CEc + j0 + tid], scol[tid]);
    }
}

__global__ __launch_bounds__(256) void k_contra_red() {
    __shared__ float sh[8];
    int i = blockIdx.x * blockDim.x + threadIdx.x;
    float v = 0.f;
    if (i < N_) {
        float ld = d_scratch[OFF_DG + i];
        v = (ld - logf(d_scratch[OFF_RE + i])) +
            (ld - logf(d_scratch[OFF_CEc + i])) + 2.f * logf((float)N_);
    }
    block_atomic_add(v, &d_scratch[OFF_ACC + A_CON], sh);
}

// ---------------------------------------------------------------------------
// supervised contrastive
// ---------------------------------------------------------------------------
__global__ __launch_bounds__(64) void k_gather(const int* __restrict__ tidx) {
    int b = blockIdx.x, t = threadIdx.x;
    int s = tidx[b];
    d_scratch[OFF_G1 + (size_t)b * 64 + t] = d_scratch[OFF_GN + (size_t)s * 64 + t];
    d_scratch[OFF_G2 + (size_t)b * 64 + t] = d_scratch[OFF_HN + (size_t)s * 64 + t];
}

__global__ __launch_bounds__(256) void k_rsa(const float* __restrict__ intra) {
    __shared__ float sh[8];
    int r = blockIdx.x;
    float v = 0.f;
    for (int j = threadIdx.x; j < M_; j += 256) v += intra[(size_t)r * M_ + j];
    int lane = threadIdx.x & 31, wid = threadIdx.x >> 5;
    v = warp_sum(v);
    if (lane == 0) sh[wid] = v;
    __syncthreads();
    if (wid == 0) {
        float x = (lane < 8) ? sh[lane] : 0.f;
        x = warp_sum(x);
        if (lane == 0) d_scratch[OFF_RSA + r] = x;
    }
}

__global__ __launch_bounds__(256) void k_sup_tile(const float* __restrict__ intra,
                                                  const float* __restrict__ inter) {
    __shared__ float Gk[64][68];
    __shared__ float Hk[64][68];
    __shared__ float s_r1[64], s_r2[64], s_c1[64], s_c2[64];
    const int tid = threadIdx.x;
    const int i0 = blockIdx.y * 64, j0 = blockIdx.x * 64;
    const float* G1 = d_scratch + OFF_G1;
    const float* G2 = d_scratch + OFF_G2;

#pragma unroll
    for (int l = 0; l < 4; l++) {
        int f4 = tid + l * 256;
        int r = f4 >> 4, c4 = (f4 & 15) << 2;
        float4 g = *(const float4*)(G1 + (size_t)(i0 + r) * 64 + c4);
        Gk[c4 + 0][r] = g.x; Gk[c4 + 1][r] = g.y;
        Gk[c4 + 2][r] = g.z; Gk[c4 + 3][r] = g.w;
        float4 h = *(const float4*)(G2 + (size_t)(j0 + r) * 64 + c4);
        Hk[c4 + 0][r] = h.x; Hk[c4 + 1][r] = h.y;
        Hk[c4 + 2][r] = h.z; Hk[c4 + 3][r] = h.w;
    }
    if (tid < 64) { s_r1[tid] = 0.f; s_r2[tid] = 0.f; s_c1[tid] = 0.f; s_c2[tid] = 0.f; }
    __syncthreads();

    const int tr = tid >> 4, tc = tid & 15;
    float acc[4][4];
#pragma unroll
    for (int i = 0; i < 4; i++)
#pragma unroll
        for (int j = 0; j < 4; j++) acc[i][j] = 0.f;

#pragma unroll 8
    for (int k = 0; k < 64; k++) {
        float4 a4 = *(const float4*)&Gk[k][tr << 2];
        float4 b4 = *(const float4*)&Hk[k][tc << 2];
        float aa[4] = {a4.x, a4.y, a4.z, a4.w};
        float bb[4] = {b4.x, b4.y, b4.z, b4.w};
#pragma unroll
        for (int i = 0; i < 4; i++)
#pragma unroll
            for (int j = 0; j < 4; j++) acc[i][j] = fmaf(aa[i], bb[j], acc[i][j]);
    }
#pragma unroll
    for (int i = 0; i < 4; i++)
#pragma unroll
        for (int j = 0; j < 4; j++) acc[i][j] = __expf(2.f * acc[i][j]);

#pragma unroll
    for (int ii = 0; ii < 4; ii++) {
        int gi = i0 + (tr << 2) + ii;
        const float4 wa = *(const float4*)(intra + (size_t)gi * M_ + j0 + (tc << 2));
        const float4 wb = *(const float4*)(inter + (size_t)gi * M_ + j0 + (tc << 2));
        float rs = acc[ii][0] * wa.x + acc[ii][1] * wa.y + acc[ii][2] * wa.z + acc[ii][3] * wa.w;
        float rn = acc[ii][0] * wb.x + acc[ii][1] * wb.y + acc[ii][2] * wb.z + acc[ii][3] * wb.w;
        atomicAdd(&s_r1[(tr << 2) + ii], rs);
        atomicAdd(&s_r2[(tr << 2) + ii], rn);
    }
#pragma unroll
    for (int jj = 0; jj < 4; jj++) {
        int gj = j0 + (tc << 2) + jj;
        const float4 wa = *(const float4*)(intra + (size_t)gj * M_ + i0 + (tr << 2));
        const float4 wb = *(const float4*)(inter + (size_t)gj * M_ + i0 + (tr << 2));
        float cs = acc[0][jj] * wa.x + acc[1][jj] * wa.y + acc[2][jj] * wa.z + acc[3][jj] * wa.w;
        float cn = acc[0][jj] * wb.x + acc[1][jj] * wb.y + acc[2][jj] * wb.z + acc[3][jj] * wb.w;
        atomicAdd(&s_c1[(tc << 2) + jj], cs);
        atomicAdd(&s_c2[(tc << 2) + jj], cn);
    }
    __syncthreads();
    if (tid < 64) {
        atomicAdd(&d_scratch[OFF_SP1 + i0 + tid], s_r1[tid]);
        atomicAdd(&d_scratch[OFF_SN1 + i0 + tid], s_r2[tid]);
        atomicAdd(&d_scratch[OFF_SP2 + j0 + tid], s_c1[tid]);
        atomicAdd(&d_scratch[OFF_SN2 + j0 + tid], s_c2[tid]);
    }
}

__global__ __launch_bounds__(256) void k_sup_red() {
    __shared__ float sh[8];
    int i = blockIdx.x * blockDim.x + threadIdx.x;
    float v = 0.f;
    if (i < M_) {
        float lM = logf((float)(M_ - 1));
        float lr = logf(d_scratch[OFF_RSA + i]);
        float sp1 = d_scratch[OFF_SP1 + i], sn1 = d_scratch[OFF_SN1 + i];
        float sp2 = d_scratch[OFF_SP2 + i], sn2 = d_scratch[OFF_SN2 + i];
        v = (logf(sp1) - lr - logf(sn1 + sp1) + lM) +
            (logf(sp2) - lr - logf(sn2 + sp2) + lM);
    }
    block_atomic_add(v, &d_scratch[OFF_ACC + A_SUP], sh);
}

// ---------------------------------------------------------------------------
// weight decay
// ---------------------------------------------------------------------------
__global__ __launch_bounds__(256) void k_wd(const float* __restrict__ W0,
                                            const float* __restrict__ b0,
                                            const float* __restrict__ W1,
                                            const float* __restrict__ b1,
                                            const float* __restrict__ Wc,
                                            const float* __restrict__ bc) {
    __shared__ float sh[8];
    float v = 0.f;
    const int total = 65536 + 256 + 16384 + 64 + 128 + 1;
    for (int idx = blockIdx.x * blockDim.x + threadIdx.x; idx < total;
         idx += gridDim.x * blockDim.x) {
        float x;
        if (idx < 65536)      x = W0[idx];
        else if (idx < 65792) x = b0[idx - 65536];
        else if (idx < 82176) x = W1[idx - 65792];
        else if (idx < 82240) x = b1[idx - 82176];
        else if (idx < 82368) x = Wc[idx - 82240];
        else                  x = bc[0];
        v += x * x;
    }
    block_atomic_add(v, &d_scratch[OFF_ACC + A_WDS], sh);
}

// ---------------------------------------------------------------------------
// finalize
// ---------------------------------------------------------------------------
__global__ void k_final(float* __restrict__ outp) {
    float lossce = d_scratch[OFF_ACC + A_CE] / (float)N_;
    float pe = -(d_scratch[OFF_ACC + A_LS1] + d_scratch[OFF_ACC + A_LS2]) / (float)E_;
    float con = -0.9f * (d_scratch[OFF_ACC + A_CON] / (2.f * (float)N_));
    float sup = -0.9f * (d_scratch[OFF_ACC + A_SUP] / (2.f * (float)M_));
    float wd  = 5e-4f * 0.5f * d_scratch[OFF_ACC + A_WDS];
    outp[(size_t)N_ * C_]     = lossce + 0.4f * pe + con + sup + wd;
    outp[(size_t)N_ * C_ + 1] = d_scratch[OFF_ACC + A_ACCU] / (float)N_;
}

// ---------------------------------------------------------------------------
// launch
// ---------------------------------------------------------------------------
extern "C" void kernel_launch(void* const* d_in, const int* in_sizes, int n_in,
                              void* d_out, int out_size) {
    const float* features = (const float*)d_in[0];
    const float* support  = (const float*)d_in[1];
    const float* labels   = (const float*)d_in[2];
    const float* intra    = (const float*)d_in[3];
    const float* inter    = (const float*)d_in[4];
    const float* W0  = (const float*)d_in[5];
    const float* b0  = (const float*)d_in[6];
    const float* W1  = (const float*)d_in[7];
    const float* b1  = (const float*)d_in[8];
    const float* Wh0 = (const float*)d_in[9];
    const float* bh0 = (const float*)d_in[10];
    const float* Wh1 = (const float*)d_in[11];
    const float* bh1 = (const float*)d_in[12];
    const float* Wc  = (const float*)d_in[13];
    const float* bc  = (const float*)d_in[14];
    const int* ei    = (const int*)d_in[15];
    const int* ej    = (const int*)d_in[16];
    const int* tidx  = (const int*)d_in[17];
    const int* mask  = (const int*)d_in[18];
    float* outp = (float*)d_out;

    float* scr = nullptr;
    cudaGetSymbolAddress((void**)&scr, d_scratch);
    __nv_bfloat16 *Sh, *Sl, *Xh, *Xl, *Wch, *Wcl, *Bbh, *Bbl;
    __nv_bfloat16 *XWh, *XWl, *Hh, *Hl, *HWh, *HWl;
    cudaGetSymbolAddress((void**)&Sh, d_Sh);   cudaGetSymbolAddress((void**)&Sl, d_Sl);
    cudaGetSymbolAddress((void**)&Xh, d_Xh);   cudaGetSymbolAddress((void**)&Xl, d_Xl);
    cudaGetSymbolAddress((void**)&Wch, d_Wch); cudaGetSymbolAddress((void**)&Wcl, d_Wcl);
    cudaGetSymbolAddress((void**)&Bbh, d_Bbh); cudaGetSymbolAddress((void**)&Bbl, d_Bbl);
    cudaGetSymbolAddress((void**)&XWh, d_XWh); cudaGetSymbolAddress((void**)&XWl, d_XWl);
    cudaGetSymbolAddress((void**)&Hh, d_Hh);   cudaGetSymbolAddress((void**)&Hl, d_Hl);
    cudaGetSymbolAddress((void**)&HWh, d_HWh); cudaGetSymbolAddress((void**)&HWl, d_HWl);

    // dynamic smem sizes per instantiation
    constexpr int SM_128_128 = 3 * (2 * 128 * 40 + 2 * 128 * 40) * 2;  // 122880
    constexpr int SM_128_256 = 3 * (2 * 128 * 40 + 2 * 256 * 40) * 2;  // 184320
    constexpr int SM_64_128  = 4 * (2 * 64 * 40 + 2 * 128 * 40) * 2;   // 122880
    constexpr int SM_CONTRA  = 4 * 128 * 72 * 2;                       // 73728
    cudaFuncSetAttribute(k_bgemm<128, 128, 3>, cudaFuncAttributeMaxDynamicSharedMemorySize, SM_128_128);
    cudaFuncSetAttribute(k_bgemm<128, 256, 3>, cudaFuncAttributeMaxDynamicSharedMemorySize, SM_128_256);
    cudaFuncSetAttribute(k_bgemm<64, 128, 4>,  cudaFuncAttributeMaxDynamicSharedMemorySize, SM_64_128);
    cudaFuncSetAttribute(k_contra_mma, cudaFuncAttributeMaxDynamicSharedMemorySize, SM_CONTRA);

    // zero accumulators (inside graph)
    k_zero<<<(2 * N_ + 255) / 256, 256>>>(scr + OFF_RE, 2 * N_);
    k_zero<<<(4 * M_ + 255) / 256, 256>>>(scr + OFF_SP1, 4 * M_);
    k_zero<<<1, 64>>>(scr + OFF_ACC, 64);

    // operand splits
    k_split<<<2048, 256>>>(support, Sh, Sl, (size_t)N_ * N_ / 4);
    k_split<<<2048, 256>>>(features, Xh, Xl, (size_t)N_ * 256 / 4);
    k_prep<<<512, 256>>>(W0, Wh0, W1, Wh1, b0, bh0, b1, bh1);
    k_masksum<<<32, 256>>>(mask);

    // G1: XWt[512,8192] = (X @ Wcat)^T   -> pair, transposed
    k_bgemm<128, 128, 3><<<dim3(4, 64), 256, SM_128_128>>>(
        Xh, Xl, 256, Wch, Wcl, 256, nullptr, nullptr,
        XWh, XWl, 8192, 256, /*trans|pair*/ 6);

    // G2: H[8192,512] = relu(S @ XW + bcat)  -> pair
    k_bgemm<128, 256, 3><<<dim3(2, 64), 256, SM_128_256>>>(
        Sh, Sl, 8192, XWh, XWl, 8192, scr + OFF_BCAT, nullptr,
        Hh, Hl, 512, 8192, /*relu|pair*/ 5);

    // G3: HWt[128,8192] = (H @ Bblk^T)^T  -> pair, transposed
    k_bgemm<128, 128, 3><<<dim3(1, 64), 256, SM_128_128>>>(
        Hh, Hl, 512, Bbh, Bbl, 512, nullptr, nullptr,
        HWh, HWl, 8192, 512, /*trans|pair*/ 6);

    // G4: Y[8192,128] = S @ HW + bcat2  -> fp32
    k_bgemm<64, 128, 4><<<dim3(1, 128), 256, SM_64_128>>>(
        Sh, Sl, 8192, HWh, HWl, 8192, scr + OFF_BCAT2,
        scr + OFF_Y, nullptr, nullptr, 128, 8192, 0);

    k_rownorm<<<N_, 32>>>(labels, Wc, bc, mask, outp);
    k_edges<<<256, 256>>>(ei, ej, bc);

    k_contra_mma<<<dim3(64, 64), 256, SM_CONTRA>>>();
    k_contra_red<<<32, 256>>>();

    k_gather<<<M_, 64>>>(tidx);
    k_rsa<<<M_, 256>>>(intra);
    k_sup_tile<<<dim3(32, 32), 256>>>(intra, inter);
    k_sup_red<<<8, 256>>>();

    k_wd<<<64, 256>>>(W0, b0, W1, b1, Wc, bc);
    k_final<<<1, 1>>>(outp);
}